// round 1
// baseline (speedup 1.0000x reference)
#include <cuda_runtime.h>
#include <math.h>

#define SEQ 2048
#define DM  4096
#define NH  32
#define NKV 8
#define HD  128
#define KVD (NKV*HD)       // 1024
#define NEG_BIG -1.0e9f

// scratch (static device globals; no allocation at runtime)
__device__ float g_q  [SEQ*DM];    // 32 MB
__device__ float g_k  [SEQ*KVD];   //  8 MB
__device__ float g_v  [SEQ*KVD];   //  8 MB
__device__ float g_qT [SEQ*DM];    // 32 MB  [NH][HD][SEQ]
__device__ float g_kT [SEQ*KVD];   //  8 MB  [NKV][HD][SEQ]
__device__ float g_att[SEQ*DM];    // 32 MB

// ---------------------------------------------------------------------------
// C[M,N] = A[M,K] * B[N,K]^T   (both row-major, K contiguous)
// 128x128 tile, BK=8, 256 threads, 8x8 microtile
// ---------------------------------------------------------------------------
__global__ __launch_bounds__(256) void gemm_nt(const float* __restrict__ A,
                                               const float* __restrict__ B,
                                               float* __restrict__ C,
                                               int M, int N, int K)
{
    __shared__ float As[8][128];
    __shared__ float Bs[8][128];

    const int tid = threadIdx.x;
    const int tx = tid & 15;
    const int ty = tid >> 4;

    const float* Ab = A + (size_t)blockIdx.y * 128 * K;
    const float* Bb = B + (size_t)blockIdx.x * 128 * K;

    float acc[8][8];
#pragma unroll
    for (int i = 0; i < 8; i++)
#pragma unroll
        for (int j = 0; j < 8; j++) acc[i][j] = 0.f;

    const int lr = tid >> 1;          // 0..127
    const int lk = (tid & 1) * 4;     // 0 or 4

    for (int k0 = 0; k0 < K; k0 += 8) {
        float4 a = *(const float4*)(Ab + (size_t)lr * K + k0 + lk);
        float4 b = *(const float4*)(Bb + (size_t)lr * K + k0 + lk);
        As[lk + 0][lr] = a.x; As[lk + 1][lr] = a.y;
        As[lk + 2][lr] = a.z; As[lk + 3][lr] = a.w;
        Bs[lk + 0][lr] = b.x; Bs[lk + 1][lr] = b.y;
        Bs[lk + 2][lr] = b.z; Bs[lk + 3][lr] = b.w;
        __syncthreads();

#pragma unroll
        for (int kk = 0; kk < 8; kk++) {
            float ar[8], br[8];
            *(float4*)(ar)     = *(const float4*)&As[kk][ty * 8];
            *(float4*)(ar + 4) = *(const float4*)&As[kk][ty * 8 + 4];
            *(float4*)(br)     = *(const float4*)&Bs[kk][tx * 8];
            *(float4*)(br + 4) = *(const float4*)&Bs[kk][tx * 8 + 4];
#pragma unroll
            for (int i = 0; i < 8; i++)
#pragma unroll
                for (int j = 0; j < 8; j++)
                    acc[i][j] = fmaf(ar[i], br[j], acc[i][j]);
        }
        __syncthreads();
    }

    float* Cb = C + (size_t)(blockIdx.y * 128 + ty * 8) * N + blockIdx.x * 128 + tx * 8;
#pragma unroll
    for (int i = 0; i < 8; i++) {
        *(float4*)(Cb + (size_t)i * N)     = make_float4(acc[i][0], acc[i][1], acc[i][2], acc[i][3]);
        *(float4*)(Cb + (size_t)i * N + 4) = make_float4(acc[i][4], acc[i][5], acc[i][6], acc[i][7]);
    }
}

// ---------------------------------------------------------------------------
// RoPE in-place on q [SEQ][NH][HD] and k [SEQ][NKV][HD]
// pair index i in 0..63 maps to elements (2i, 2i+1)
// ---------------------------------------------------------------------------
__global__ void rope_kernel(float* __restrict__ q, float* __restrict__ k,
                            const float* __restrict__ fcos,
                            const float* __restrict__ fsin)
{
    const int QP = SEQ * NH  * (HD / 2);
    const int KP = SEQ * NKV * (HD / 2);
    int idx = blockIdx.x * blockDim.x + threadIdx.x;
    if (idx < QP) {
        int i = idx & 63;
        int h = (idx >> 6) & (NH - 1);
        int s = idx >> 11;  // /(64*32)
        float c  = fcos[s * 64 + i];
        float sn = fsin[s * 64 + i];
        float2* p = (float2*)(q + (size_t)s * DM + h * HD + 2 * i);
        float2 xv = *p;
        float2 o;
        o.x = xv.x * c - xv.y * sn;
        o.y = xv.x * sn + xv.y * c;
        *p = o;
    } else if (idx < QP + KP) {
        int t = idx - QP;
        int i = t & 63;
        int h = (t >> 6) & (NKV - 1);
        int s = t >> 9;   // /(64*8)
        float c  = fcos[s * 64 + i];
        float sn = fsin[s * 64 + i];
        float2* p = (float2*)(k + (size_t)s * KVD + h * HD + 2 * i);
        float2 xv = *p;
        float2 o;
        o.x = xv.x * c - xv.y * sn;
        o.y = xv.x * sn + xv.y * c;
        *p = o;
    }
}

// ---------------------------------------------------------------------------
// transpose: in [R][C] row-major -> out [C][R]
// ---------------------------------------------------------------------------
__global__ void transpose_kernel(const float* __restrict__ in,
                                 float* __restrict__ out, int R, int C)
{
    __shared__ float t[32][33];
    int bx = blockIdx.x * 32;  // col tile
    int by = blockIdx.y * 32;  // row tile
    int x = bx + threadIdx.x;
#pragma unroll
    for (int i = 0; i < 32; i += 8)
        t[threadIdx.y + i][threadIdx.x] = in[(size_t)(by + threadIdx.y + i) * C + x];
    __syncthreads();
    int x2 = by + threadIdx.x;
#pragma unroll
    for (int i = 0; i < 32; i += 8)
        out[(size_t)(bx + threadIdx.y + i) * R + x2] = t[threadIdx.x][threadIdx.y + i];
}

// ---------------------------------------------------------------------------
// flash attention, fp32, causal, GQA (4 q heads per kv head)
// qT: [NH][HD][SEQ], kT: [NKV][HD][SEQ], v: [SEQ][NKV][HD], out: [SEQ][DM]
// block: 256 threads = 16x16; Q tile 64 rows, K tile 64 keys; 4x4 score
// microtile, O microtile 4 rows x 8 dims.
// ---------------------------------------------------------------------------
#define BM 64
#define BN 64
#define PP 68   // padded P row

__global__ __launch_bounds__(256) void flash_kernel(
    const float* __restrict__ qT, const float* __restrict__ kT,
    const float* __restrict__ v,  float* __restrict__ out)
{
    extern __shared__ float sm[];
    float* Qs = sm;                 // [HD][BM] d-major
    float* Ks = Qs + HD * BM;       // [HD][BN] d-major
    float* Vs = Ks + HD * BN;       // [BN][HD] key-major
    float* Ps = Vs + BN * HD;       // [BM][PP] row-major probs

    const int h   = blockIdx.y;
    const int qb  = blockIdx.x;
    const int q0  = qb * BM;
    const int kvh = h >> 2;
    const int tid = threadIdx.x;
    const int tx  = tid & 15;
    const int ty  = tid >> 4;

    // stage Q tile: Qs[d][r] <- qT[h][d][q0+r]  (coalesced, conflict-free)
    const float* qTb = qT + ((size_t)h * HD) * SEQ + q0;
    for (int i = tid; i < HD * BM / 4; i += 256) {
        int d = i >> 4;
        int r = (i & 15) << 2;
        *(float4*)&Qs[d * BM + r] = *(const float4*)(qTb + (size_t)d * SEQ + r);
    }

    float o[4][8];
#pragma unroll
    for (int i = 0; i < 4; i++)
#pragma unroll
        for (int j = 0; j < 8; j++) o[i][j] = 0.f;
    float m[4], l[4];
#pragma unroll
    for (int i = 0; i < 4; i++) { m[i] = -3.0e38f; l[i] = 0.f; }

    const float sc = 0.088388347648318447f;  // 1/sqrt(128)

    for (int kb = 0; kb <= qb; kb++) {
        const int k0 = kb * BN;
        const float* kTb = kT + ((size_t)kvh * HD) * SEQ + k0;
        for (int i = tid; i < HD * BN / 4; i += 256) {
            int d = i >> 4;
            int c = (i & 15) << 2;
            *(float4*)&Ks[d * BN + c] = *(const float4*)(kTb + (size_t)d * SEQ + c);
        }
        const float* vb = v + (size_t)k0 * KVD + kvh * HD;
        for (int i = tid; i < BN * HD / 4; i += 256) {
            int c = i >> 5;
            int d = (i & 31) << 2;
            *(float4*)&Vs[c * HD + d] = *(const float4*)(vb + (size_t)c * KVD + d);
        }
        __syncthreads();

        // S = Q K^T  (4x4 per thread)
        float s4[4][4];
#pragma unroll
        for (int i = 0; i < 4; i++)
#pragma unroll
            for (int j = 0; j < 4; j++) s4[i][j] = 0.f;

#pragma unroll 4
        for (int d = 0; d < HD; d++) {
            float qv[4], kv[4];
            *(float4*)qv = *(const float4*)&Qs[d * BM + ty * 4];
            *(float4*)kv = *(const float4*)&Ks[d * BN + tx * 4];
#pragma unroll
            for (int i = 0; i < 4; i++)
#pragma unroll
                for (int j = 0; j < 4; j++)
                    s4[i][j] = fmaf(qv[i], kv[j], s4[i][j]);
        }

        // scale + causal mask (replicates reference: scores*sc + (-1e9) mask)
#pragma unroll
        for (int i = 0; i < 4; i++)
#pragma unroll
            for (int j = 0; j < 4; j++) {
                float sv = s4[i][j] * sc;
                if (kb == qb && (k0 + tx * 4 + j) > (q0 + ty * 4 + i)) sv += NEG_BIG;
                s4[i][j] = sv;
            }

        // online softmax
        float alpha[4];
#pragma unroll
        for (int i = 0; i < 4; i++) {
            float mx = fmaxf(fmaxf(s4[i][0], s4[i][1]), fmaxf(s4[i][2], s4[i][3]));
#pragma unroll
            for (int off = 8; off; off >>= 1)
                mx = fmaxf(mx, __shfl_xor_sync(0xffffffffu, mx, off));
            float mnew = fmaxf(m[i], mx);
            alpha[i] = __expf(m[i] - mnew);
            m[i] = mnew;
        }
        float rs[4];
#pragma unroll
        for (int i = 0; i < 4; i++) {
            float r = 0.f;
#pragma unroll
            for (int j = 0; j < 4; j++) {
                float p = __expf(s4[i][j] - m[i]);
                s4[i][j] = p;
                r += p;
            }
#pragma unroll
            for (int off = 8; off; off >>= 1)
                r += __shfl_xor_sync(0xffffffffu, r, off);
            rs[i] = r;
        }
#pragma unroll
        for (int i = 0; i < 4; i++) {
            l[i] = l[i] * alpha[i] + rs[i];
#pragma unroll
            for (int j = 0; j < 8; j++) o[i][j] *= alpha[i];
        }

        // stage P row-major
#pragma unroll
        for (int i = 0; i < 4; i++)
            *(float4*)&Ps[(ty * 4 + i) * PP + tx * 4] =
                make_float4(s4[i][0], s4[i][1], s4[i][2], s4[i][3]);
        __syncthreads();

        // O += P * V
#pragma unroll 4
        for (int c = 0; c < BN; c++) {
            float pv[4];
#pragma unroll
            for (int i = 0; i < 4; i++) pv[i] = Ps[(ty * 4 + i) * PP + c];
            float vv[8];
            *(float4*)(vv)     = *(const float4*)&Vs[c * HD + tx * 8];
            *(float4*)(vv + 4) = *(const float4*)&Vs[c * HD + tx * 8 + 4];
#pragma unroll
            for (int i = 0; i < 4; i++)
#pragma unroll
                for (int j = 0; j < 8; j++)
                    o[i][j] = fmaf(pv[i], vv[j], o[i][j]);
        }
        __syncthreads();
    }

    // write normalized O
#pragma unroll
    for (int i = 0; i < 4; i++) {
        float inv = 1.f / l[i];
        float* ob = out + (size_t)(q0 + ty * 4 + i) * DM + h * HD + tx * 8;
        *(float4*)(ob)     = make_float4(o[i][0] * inv, o[i][1] * inv, o[i][2] * inv, o[i][3] * inv);
        *(float4*)(ob + 4) = make_float4(o[i][4] * inv, o[i][5] * inv, o[i][6] * inv, o[i][7] * inv);
    }
}

// ---------------------------------------------------------------------------
extern "C" void kernel_launch(void* const* d_in, const int* in_sizes, int n_in,
                              void* d_out, int out_size)
{
    const float* x    = (const float*)d_in[0];
    const float* wq   = (const float*)d_in[1];
    const float* wk   = (const float*)d_in[2];
    const float* wv   = (const float*)d_in[3];
    const float* wo   = (const float*)d_in[4];
    const float* fcos = (const float*)d_in[7];
    const float* fsin = (const float*)d_in[8];
    float* out = (float*)d_out;

    float *q, *k, *v, *qT, *kT, *att;
    cudaGetSymbolAddress((void**)&q,   g_q);
    cudaGetSymbolAddress((void**)&k,   g_k);
    cudaGetSymbolAddress((void**)&v,   g_v);
    cudaGetSymbolAddress((void**)&qT,  g_qT);
    cudaGetSymbolAddress((void**)&kT,  g_kT);
    cudaGetSymbolAddress((void**)&att, g_att);

    // QKV projections
    gemm_nt<<<dim3(DM / 128, SEQ / 128), 256>>>(x, wq, q, SEQ, DM, DM);
    gemm_nt<<<dim3(KVD / 128, SEQ / 128), 256>>>(x, wk, k, SEQ, KVD, DM);
    gemm_nt<<<dim3(KVD / 128, SEQ / 128), 256>>>(x, wv, v, SEQ, KVD, DM);

    // RoPE on q and k
    {
        int total = SEQ * NH * (HD / 2) + SEQ * NKV * (HD / 2);
        rope_kernel<<<(total + 255) / 256, 256>>>(q, k, fcos, fsin);
    }

    // transposes for d-major staging
    transpose_kernel<<<dim3(DM / 32, SEQ / 32), dim3(32, 8)>>>(q, qT, SEQ, DM);
    transpose_kernel<<<dim3(KVD / 32, SEQ / 32), dim3(32, 8)>>>(k, kT, SEQ, KVD);

    // flash attention
    {
        size_t smem = (size_t)(HD * BM + HD * BN + BN * HD + BM * PP) * sizeof(float);
        cudaFuncSetAttribute(flash_kernel, cudaFuncAttributeMaxDynamicSharedMemorySize, (int)smem);
        flash_kernel<<<dim3(SEQ / BM, NH), 256, smem>>>(qT, kT, v, att);
    }

    // output projection
    gemm_nt<<<dim3(DM / 128, SEQ / 128), 256>>>(att, wo, out, SEQ, DM, DM);
}

// round 3
// speedup vs baseline: 1.9071x; 1.9071x over previous
#include <cuda_runtime.h>
#include <cstdint>
#include <math.h>

#define SEQ 2048
#define DM  4096
#define NH  32
#define NKV 8
#define HD  128
#define KVD (NKV*HD)       // 1024
#define NEG_BIG -1.0e9f

// scratch (static device globals; no allocation at runtime)
__device__ float g_q  [SEQ*DM];
__device__ float g_k  [SEQ*KVD];
__device__ float g_v  [SEQ*KVD];
__device__ float g_qT [SEQ*DM];    // [NH][HD][SEQ]
__device__ float g_kT [SEQ*KVD];   // [NKV][HD][SEQ]
__device__ float g_att[SEQ*DM];

// round-to-nearest tf32 conversion (unbiased)
__device__ __forceinline__ uint32_t f2tf32(float f) {
    uint32_t r;
    asm("cvt.rna.tf32.f32 %0, %1;" : "=r"(r) : "f"(f));
    return r;
}

// ---------------------------------------------------------------------------
// tf32 mma.sync GEMM: C[M,N] = A[M,K] * B[N,K]^T  (row-major, K contiguous)
// CTA 128x128x32, 256 threads (8 warps, 2Mx4N), warp tile 64x32,
// m16n8k8 tf32 MMA, padded smem (stride 36) for conflict-free fragment LDS,
// double-buffered smem with register-staged global prefetch.
// ---------------------------------------------------------------------------
#define GT1 (128*36)      // one tile in words
#define GT2 (2*GT1)       // one stage (A+B)
#define GEMM_SMEM (2*GT2*4)  // 73728 bytes

__global__ __launch_bounds__(256) void gemm_mma(
    const float* __restrict__ A, const float* __restrict__ B,
    float* __restrict__ C, int M, int N, int K)
{
    extern __shared__ uint32_t smq[];

    const int tid  = threadIdx.x;
    const int lane = tid & 31;
    const int warp = tid >> 5;
    const int wm = warp & 1;       // 2 warps along M
    const int wn = warp >> 1;      // 4 warps along N
    const int lg = lane >> 2;      // 0..7
    const int lc = lane & 3;       // 0..3

    // global->smem loader mapping: 2 threads per row, 16 cols each
    const int rowL = tid >> 1;           // 0..127
    const int cg   = (tid & 1) << 4;     // 0 or 16

    const float* Ag = A + (size_t)(blockIdx.y * 128 + rowL) * K + cg;
    const float* Bg = B + (size_t)(blockIdx.x * 128 + rowL) * K + cg;

    float acc[4][4][4];
#pragma unroll
    for (int mi = 0; mi < 4; mi++)
#pragma unroll
        for (int ni = 0; ni < 4; ni++)
#pragma unroll
            for (int r = 0; r < 4; r++) acc[mi][ni][r] = 0.f;

    float4 ra[4], rb[4];
    // prologue: load k-tile 0 into stage 0
#pragma unroll
    for (int j = 0; j < 4; j++) {
        ra[j] = *(const float4*)(Ag + j * 4);
        rb[j] = *(const float4*)(Bg + j * 4);
    }
    {
        uint32_t* As0 = smq;
        uint32_t* Bs0 = smq + GT1;
#pragma unroll
        for (int j = 0; j < 4; j++) {
            *(uint4*)&As0[rowL * 36 + cg + j * 4] =
                make_uint4(f2tf32(ra[j].x), f2tf32(ra[j].y), f2tf32(ra[j].z), f2tf32(ra[j].w));
            *(uint4*)&Bs0[rowL * 36 + cg + j * 4] =
                make_uint4(f2tf32(rb[j].x), f2tf32(rb[j].y), f2tf32(rb[j].z), f2tf32(rb[j].w));
        }
    }
    __syncthreads();

    const int kiters = K / 32;
    for (int kt = 0; kt < kiters; kt++) {
        const int st = kt & 1;
        if (kt + 1 < kiters) {
#pragma unroll
            for (int j = 0; j < 4; j++) {
                ra[j] = *(const float4*)(Ag + (kt + 1) * 32 + j * 4);
                rb[j] = *(const float4*)(Bg + (kt + 1) * 32 + j * 4);
            }
        }
        const uint32_t* As = smq + st * GT2;
        const uint32_t* Bs = As + GT1;

#pragma unroll
        for (int k0 = 0; k0 < 32; k0 += 8) {
            uint32_t af[4][4], bf[4][2];
#pragma unroll
            for (int mi = 0; mi < 4; mi++) {
                int r = wm * 64 + mi * 16 + lg;
                af[mi][0] = As[r * 36 + k0 + lc];
                af[mi][1] = As[(r + 8) * 36 + k0 + lc];
                af[mi][2] = As[r * 36 + k0 + lc + 4];
                af[mi][3] = As[(r + 8) * 36 + k0 + lc + 4];
            }
#pragma unroll
            for (int ni = 0; ni < 4; ni++) {
                int n = wn * 32 + ni * 8 + lg;
                bf[ni][0] = Bs[n * 36 + k0 + lc];
                bf[ni][1] = Bs[n * 36 + k0 + lc + 4];
            }
#pragma unroll
            for (int mi = 0; mi < 4; mi++)
#pragma unroll
                for (int ni = 0; ni < 4; ni++)
                    asm volatile(
                        "mma.sync.aligned.m16n8k8.row.col.f32.tf32.tf32.f32 "
                        "{%0,%1,%2,%3}, {%4,%5,%6,%7}, {%8,%9}, {%0,%1,%2,%3};"
                        : "+f"(acc[mi][ni][0]), "+f"(acc[mi][ni][1]),
                          "+f"(acc[mi][ni][2]), "+f"(acc[mi][ni][3])
                        : "r"(af[mi][0]), "r"(af[mi][1]), "r"(af[mi][2]), "r"(af[mi][3]),
                          "r"(bf[ni][0]), "r"(bf[ni][1]));
        }
        __syncthreads();
        if (kt + 1 < kiters) {
            uint32_t* As2 = smq + (st ^ 1) * GT2;
            uint32_t* Bs2 = As2 + GT1;
#pragma unroll
            for (int j = 0; j < 4; j++) {
                *(uint4*)&As2[rowL * 36 + cg + j * 4] =
                    make_uint4(f2tf32(ra[j].x), f2tf32(ra[j].y), f2tf32(ra[j].z), f2tf32(ra[j].w));
                *(uint4*)&Bs2[rowL * 36 + cg + j * 4] =
                    make_uint4(f2tf32(rb[j].x), f2tf32(rb[j].y), f2tf32(rb[j].z), f2tf32(rb[j].w));
            }
            __syncthreads();
        }
    }

    // epilogue: direct stores (c0,c1) / (c2,c3) pairs
#pragma unroll
    for (int mi = 0; mi < 4; mi++) {
        int r0 = blockIdx.y * 128 + wm * 64 + mi * 16 + lg;
#pragma unroll
        for (int ni = 0; ni < 4; ni++) {
            int c = blockIdx.x * 128 + wn * 32 + ni * 8 + lc * 2;
            *(float2*)&C[(size_t)r0 * N + c]       = make_float2(acc[mi][ni][0], acc[mi][ni][1]);
            *(float2*)&C[(size_t)(r0 + 8) * N + c] = make_float2(acc[mi][ni][2], acc[mi][ni][3]);
        }
    }
}

// ---------------------------------------------------------------------------
// RoPE in-place on q [SEQ][NH][HD] and k [SEQ][NKV][HD]
// ---------------------------------------------------------------------------
__global__ void rope_kernel(float* __restrict__ q, float* __restrict__ k,
                            const float* __restrict__ fcos,
                            const float* __restrict__ fsin)
{
    const int QP = SEQ * NH  * (HD / 2);
    const int KP = SEQ * NKV * (HD / 2);
    int idx = blockIdx.x * blockDim.x + threadIdx.x;
    if (idx < QP) {
        int i = idx & 63;
        int h = (idx >> 6) & (NH - 1);
        int s = idx >> 11;
        float c  = fcos[s * 64 + i];
        float sn = fsin[s * 64 + i];
        float2* p = (float2*)(q + (size_t)s * DM + h * HD + 2 * i);
        float2 xv = *p;
        float2 o;
        o.x = xv.x * c - xv.y * sn;
        o.y = xv.x * sn + xv.y * c;
        *p = o;
    } else if (idx < QP + KP) {
        int t = idx - QP;
        int i = t & 63;
        int h = (t >> 6) & (NKV - 1);
        int s = t >> 9;
        float c  = fcos[s * 64 + i];
        float sn = fsin[s * 64 + i];
        float2* p = (float2*)(k + (size_t)s * KVD + h * HD + 2 * i);
        float2 xv = *p;
        float2 o;
        o.x = xv.x * c - xv.y * sn;
        o.y = xv.x * sn + xv.y * c;
        *p = o;
    }
}

// ---------------------------------------------------------------------------
__global__ void transpose_kernel(const float* __restrict__ in,
                                 float* __restrict__ out, int R, int C)
{
    __shared__ float t[32][33];
    int bx = blockIdx.x * 32;
    int by = blockIdx.y * 32;
    int x = bx + threadIdx.x;
#pragma unroll
    for (int i = 0; i < 32; i += 8)
        t[threadIdx.y + i][threadIdx.x] = in[(size_t)(by + threadIdx.y + i) * C + x];
    __syncthreads();
    int x2 = by + threadIdx.x;
#pragma unroll
    for (int i = 0; i < 32; i += 8)
        out[(size_t)(bx + threadIdx.y + i) * R + x2] = t[threadIdx.x][threadIdx.y + i];
}

// ---------------------------------------------------------------------------
// flash attention, fp32, causal, GQA  (unchanged from round 1 — passed)
// ---------------------------------------------------------------------------
#define BM 64
#define BN 64
#define PP 68

__global__ __launch_bounds__(256) void flash_kernel(
    const float* __restrict__ qT, const float* __restrict__ kT,
    const float* __restrict__ v,  float* __restrict__ out)
{
    extern __shared__ float sm[];
    float* Qs = sm;
    float* Ks = Qs + HD * BM;
    float* Vs = Ks + HD * BN;
    float* Ps = Vs + BN * HD;

    const int h   = blockIdx.y;
    const int qb  = blockIdx.x;
    const int q0  = qb * BM;
    const int kvh = h >> 2;
    const int tid = threadIdx.x;
    const int tx  = tid & 15;
    const int ty  = tid >> 4;

    const float* qTb = qT + ((size_t)h * HD) * SEQ + q0;
    for (int i = tid; i < HD * BM / 4; i += 256) {
        int d = i >> 4;
        int r = (i & 15) << 2;
        *(float4*)&Qs[d * BM + r] = *(const float4*)(qTb + (size_t)d * SEQ + r);
    }

    float o[4][8];
#pragma unroll
    for (int i = 0; i < 4; i++)
#pragma unroll
        for (int j = 0; j < 8; j++) o[i][j] = 0.f;
    float m[4], l[4];
#pragma unroll
    for (int i = 0; i < 4; i++) { m[i] = -3.0e38f; l[i] = 0.f; }

    const float sc = 0.088388347648318447f;

    for (int kb = 0; kb <= qb; kb++) {
        const int k0 = kb * BN;
        const float* kTb = kT + ((size_t)kvh * HD) * SEQ + k0;
        for (int i = tid; i < HD * BN / 4; i += 256) {
            int d = i >> 4;
            int c = (i & 15) << 2;
            *(float4*)&Ks[d * BN + c] = *(const float4*)(kTb + (size_t)d * SEQ + c);
        }
        const float* vb = v + (size_t)k0 * KVD + kvh * HD;
        for (int i = tid; i < BN * HD / 4; i += 256) {
            int c = i >> 5;
            int d = (i & 31) << 2;
            *(float4*)&Vs[c * HD + d] = *(const float4*)(vb + (size_t)c * KVD + d);
        }
        __syncthreads();

        float s4[4][4];
#pragma unroll
        for (int i = 0; i < 4; i++)
#pragma unroll
            for (int j = 0; j < 4; j++) s4[i][j] = 0.f;

#pragma unroll 4
        for (int d = 0; d < HD; d++) {
            float qv[4], kv[4];
            *(float4*)qv = *(const float4*)&Qs[d * BM + ty * 4];
            *(float4*)kv = *(const float4*)&Ks[d * BN + tx * 4];
#pragma unroll
            for (int i = 0; i < 4; i++)
#pragma unroll
                for (int j = 0; j < 4; j++)
                    s4[i][j] = fmaf(qv[i], kv[j], s4[i][j]);
        }

#pragma unroll
        for (int i = 0; i < 4; i++)
#pragma unroll
            for (int j = 0; j < 4; j++) {
                float sv = s4[i][j] * sc;
                if (kb == qb && (k0 + tx * 4 + j) > (q0 + ty * 4 + i)) sv += NEG_BIG;
                s4[i][j] = sv;
            }

        float alpha[4];
#pragma unroll
        for (int i = 0; i < 4; i++) {
            float mx = fmaxf(fmaxf(s4[i][0], s4[i][1]), fmaxf(s4[i][2], s4[i][3]));
#pragma unroll
            for (int off = 8; off; off >>= 1)
                mx = fmaxf(mx, __shfl_xor_sync(0xffffffffu, mx, off));
            float mnew = fmaxf(m[i], mx);
            alpha[i] = __expf(m[i] - mnew);
            m[i] = mnew;
        }
        float rs[4];
#pragma unroll
        for (int i = 0; i < 4; i++) {
            float r = 0.f;
#pragma unroll
            for (int j = 0; j < 4; j++) {
                float p = __expf(s4[i][j] - m[i]);
                s4[i][j] = p;
                r += p;
            }
#pragma unroll
            for (int off = 8; off; off >>= 1)
                r += __shfl_xor_sync(0xffffffffu, r, off);
            rs[i] = r;
        }
#pragma unroll
        for (int i = 0; i < 4; i++) {
            l[i] = l[i] * alpha[i] + rs[i];
#pragma unroll
            for (int j = 0; j < 8; j++) o[i][j] *= alpha[i];
        }

#pragma unroll
        for (int i = 0; i < 4; i++)
            *(float4*)&Ps[(ty * 4 + i) * PP + tx * 4] =
                make_float4(s4[i][0], s4[i][1], s4[i][2], s4[i][3]);
        __syncthreads();

#pragma unroll 4
        for (int c = 0; c < BN; c++) {
            float pv[4];
#pragma unroll
            for (int i = 0; i < 4; i++) pv[i] = Ps[(ty * 4 + i) * PP + c];
            float vv[8];
            *(float4*)(vv)     = *(const float4*)&Vs[c * HD + tx * 8];
            *(float4*)(vv + 4) = *(const float4*)&Vs[c * HD + tx * 8 + 4];
#pragma unroll
            for (int i = 0; i < 4; i++)
#pragma unroll
                for (int j = 0; j < 8; j++)
                    o[i][j] = fmaf(pv[i], vv[j], o[i][j]);
        }
        __syncthreads();
    }

#pragma unroll
    for (int i = 0; i < 4; i++) {
        float inv = 1.f / l[i];
        float* ob = out + (size_t)(q0 + ty * 4 + i) * DM + h * HD + tx * 8;
        *(float4*)(ob)     = make_float4(o[i][0] * inv, o[i][1] * inv, o[i][2] * inv, o[i][3] * inv);
        *(float4*)(ob + 4) = make_float4(o[i][4] * inv, o[i][5] * inv, o[i][6] * inv, o[i][7] * inv);
    }
}

// ---------------------------------------------------------------------------
extern "C" void kernel_launch(void* const* d_in, const int* in_sizes, int n_in,
                              void* d_out, int out_size)
{
    const float* x    = (const float*)d_in[0];
    const float* wq   = (const float*)d_in[1];
    const float* wk   = (const float*)d_in[2];
    const float* wv   = (const float*)d_in[3];
    const float* wo   = (const float*)d_in[4];
    const float* fcos = (const float*)d_in[7];
    const float* fsin = (const float*)d_in[8];
    float* out = (float*)d_out;

    float *q, *k, *v, *qT, *kT, *att;
    cudaGetSymbolAddress((void**)&q,   g_q);
    cudaGetSymbolAddress((void**)&k,   g_k);
    cudaGetSymbolAddress((void**)&v,   g_v);
    cudaGetSymbolAddress((void**)&qT,  g_qT);
    cudaGetSymbolAddress((void**)&kT,  g_kT);
    cudaGetSymbolAddress((void**)&att, g_att);

    cudaFuncSetAttribute(gemm_mma,
                         cudaFuncAttributeMaxDynamicSharedMemorySize, GEMM_SMEM);

    // QKV projections (tf32 mma.sync tensor path)
    gemm_mma<<<dim3(DM / 128,  SEQ / 128), 256, GEMM_SMEM>>>(x, wq, q, SEQ, DM,  DM);
    gemm_mma<<<dim3(KVD / 128, SEQ / 128), 256, GEMM_SMEM>>>(x, wk, k, SEQ, KVD, DM);
    gemm_mma<<<dim3(KVD / 128, SEQ / 128), 256, GEMM_SMEM>>>(x, wv, v, SEQ, KVD, DM);

    // RoPE
    {
        int total = SEQ * NH * (HD / 2) + SEQ * NKV * (HD / 2);
        rope_kernel<<<(total + 255) / 256, 256>>>(q, k, fcos, fsin);
    }

    // transposes for d-major staging
    transpose_kernel<<<dim3(DM / 32,  SEQ / 32), dim3(32, 8)>>>(q, qT, SEQ, DM);
    transpose_kernel<<<dim3(KVD / 32, SEQ / 32), dim3(32, 8)>>>(k, kT, SEQ, KVD);

    // flash attention (fp32)
    {
        size_t smem = (size_t)(HD * BM + HD * BN + BN * HD + BM * PP) * sizeof(float);
        cudaFuncSetAttribute(flash_kernel,
                             cudaFuncAttributeMaxDynamicSharedMemorySize, (int)smem);
        flash_kernel<<<dim3(SEQ / BM, NH), 256, smem>>>(qT, kT, v, att);
    }

    // output projection (tf32 mma.sync tensor path)
    gemm_mma<<<dim3(DM / 128, SEQ / 128), 256, GEMM_SMEM>>>(att, wo, out, SEQ, DM, DM);
}

// round 4
// speedup vs baseline: 2.1225x; 1.1130x over previous
#include <cuda_runtime.h>
#include <cstdint>
#include <math.h>

#define SEQ 2048
#define DM  4096
#define NH  32
#define NKV 8
#define HD  128
#define KVD (NKV*HD)       // 1024
#define NEG_BIG -1.0e9f

// scratch (static device globals; no allocation at runtime)
__device__ float g_q  [SEQ*DM];
__device__ float g_k  [SEQ*KVD];
__device__ float g_v  [SEQ*KVD];
__device__ float g_att[SEQ*DM];

// round-to-nearest tf32 conversion (unbiased)
__device__ __forceinline__ uint32_t f2tf32(float f) {
    uint32_t r;
    asm("cvt.rna.tf32.f32 %0, %1;" : "=r"(r) : "f"(f));
    return r;
}
__device__ __forceinline__ void mma_tf32(float* d, const uint32_t* a,
                                         const uint32_t* b) {
    asm volatile(
        "mma.sync.aligned.m16n8k8.row.col.f32.tf32.tf32.f32 "
        "{%0,%1,%2,%3}, {%4,%5,%6,%7}, {%8,%9}, {%0,%1,%2,%3};"
        : "+f"(d[0]), "+f"(d[1]), "+f"(d[2]), "+f"(d[3])
        : "r"(a[0]), "r"(a[1]), "r"(a[2]), "r"(a[3]), "r"(b[0]), "r"(b[1]));
}

// ---------------------------------------------------------------------------
// tf32 mma.sync GEMM v2: C[M,N] = A[M,K] * B[N,K]^T
// CTA 128x128, kc=16, 128 threads = 4 warps (2Mx2N), warp tile 64x64,
// padded smem stride 20 (conflict-free fragment LDS), double buffer,
// register-staged global prefetch, one __syncthreads per k-chunk.
// ---------------------------------------------------------------------------
#define GKC 16
#define GST 20                 // smem row stride (words)
#define GT1 (128*GST)          // one matrix tile (words)
#define GSTAGE (2*GT1)         // A+B stage
#define GEMM_SMEM (2*GSTAGE*4) // 40960 bytes

__global__ __launch_bounds__(128, 2) void gemm_mma(
    const float* __restrict__ A, const float* __restrict__ B,
    float* __restrict__ C, int M, int N, int K)
{
    extern __shared__ uint32_t smq[];

    const int tid  = threadIdx.x;
    const int lane = tid & 31;
    const int warp = tid >> 5;
    const int wm = warp & 1;       // 2 warps along M (64 rows each)
    const int wn = warp >> 1;      // 2 warps along N (64 cols each)
    const int lg = lane >> 2;      // 0..7
    const int lc = lane & 3;       // 0..3

    // loader: thread t owns A row t and B row t (16 floats each per chunk)
    const float* Ag = A + (size_t)(blockIdx.y * 128 + tid) * K;
    const float* Bg = B + (size_t)(blockIdx.x * 128 + tid) * K;

    float acc[4][8][4];
#pragma unroll
    for (int mi = 0; mi < 4; mi++)
#pragma unroll
        for (int ni = 0; ni < 8; ni++)
#pragma unroll
            for (int r = 0; r < 4; r++) acc[mi][ni][r] = 0.f;

    float4 ra[4], rb[4];
#pragma unroll
    for (int j = 0; j < 4; j++) {
        ra[j] = *(const float4*)(Ag + j * 4);
        rb[j] = *(const float4*)(Bg + j * 4);
    }
    {
        uint32_t* As0 = smq;
        uint32_t* Bs0 = smq + GT1;
#pragma unroll
        for (int j = 0; j < 4; j++) {
            *(uint4*)&As0[tid * GST + j * 4] =
                make_uint4(f2tf32(ra[j].x), f2tf32(ra[j].y), f2tf32(ra[j].z), f2tf32(ra[j].w));
            *(uint4*)&Bs0[tid * GST + j * 4] =
                make_uint4(f2tf32(rb[j].x), f2tf32(rb[j].y), f2tf32(rb[j].z), f2tf32(rb[j].w));
        }
    }
    __syncthreads();

    const int kiters = K / GKC;
    for (int kt = 0; kt < kiters; kt++) {
        const int st = kt & 1;
        if (kt + 1 < kiters) {
#pragma unroll
            for (int j = 0; j < 4; j++) {
                ra[j] = *(const float4*)(Ag + (kt + 1) * GKC + j * 4);
                rb[j] = *(const float4*)(Bg + (kt + 1) * GKC + j * 4);
            }
        }
        const uint32_t* As = smq + st * GSTAGE;
        const uint32_t* Bs = As + GT1;

#pragma unroll
        for (int k0 = 0; k0 < GKC; k0 += 8) {
            uint32_t af[4][4], bf[8][2];
#pragma unroll
            for (int mi = 0; mi < 4; mi++) {
                int r = wm * 64 + mi * 16 + lg;
                af[mi][0] = As[r * GST + k0 + lc];
                af[mi][1] = As[(r + 8) * GST + k0 + lc];
                af[mi][2] = As[r * GST + k0 + lc + 4];
                af[mi][3] = As[(r + 8) * GST + k0 + lc + 4];
            }
#pragma unroll
            for (int ni = 0; ni < 8; ni++) {
                int n = wn * 64 + ni * 8 + lg;
                bf[ni][0] = Bs[n * GST + k0 + lc];
                bf[ni][1] = Bs[n * GST + k0 + lc + 4];
            }
#pragma unroll
            for (int mi = 0; mi < 4; mi++)
#pragma unroll
                for (int ni = 0; ni < 8; ni++)
                    mma_tf32(acc[mi][ni], af[mi], bf[ni]);
        }

        if (kt + 1 < kiters) {
            uint32_t* As2 = smq + (st ^ 1) * GSTAGE;
            uint32_t* Bs2 = As2 + GT1;
#pragma unroll
            for (int j = 0; j < 4; j++) {
                *(uint4*)&As2[tid * GST + j * 4] =
                    make_uint4(f2tf32(ra[j].x), f2tf32(ra[j].y), f2tf32(ra[j].z), f2tf32(ra[j].w));
                *(uint4*)&Bs2[tid * GST + j * 4] =
                    make_uint4(f2tf32(rb[j].x), f2tf32(rb[j].y), f2tf32(rb[j].z), f2tf32(rb[j].w));
            }
        }
        __syncthreads();
    }

#pragma unroll
    for (int mi = 0; mi < 4; mi++) {
        int r0 = blockIdx.y * 128 + wm * 64 + mi * 16 + lg;
#pragma unroll
        for (int ni = 0; ni < 8; ni++) {
            int c = blockIdx.x * 128 + wn * 64 + ni * 8 + lc * 2;
            *(float2*)&C[(size_t)r0 * N + c]       = make_float2(acc[mi][ni][0], acc[mi][ni][1]);
            *(float2*)&C[(size_t)(r0 + 8) * N + c] = make_float2(acc[mi][ni][2], acc[mi][ni][3]);
        }
    }
}

// ---------------------------------------------------------------------------
// RoPE in-place on q [SEQ][NH][HD] and k [SEQ][NKV][HD]
// ---------------------------------------------------------------------------
__global__ void rope_kernel(float* __restrict__ q, float* __restrict__ k,
                            const float* __restrict__ fcos,
                            const float* __restrict__ fsin)
{
    const int QP = SEQ * NH  * (HD / 2);
    const int KP = SEQ * NKV * (HD / 2);
    int idx = blockIdx.x * blockDim.x + threadIdx.x;
    if (idx < QP) {
        int i = idx & 63;
        int h = (idx >> 6) & (NH - 1);
        int s = idx >> 11;
        float c  = fcos[s * 64 + i];
        float sn = fsin[s * 64 + i];
        float2* p = (float2*)(q + (size_t)s * DM + h * HD + 2 * i);
        float2 xv = *p;
        float2 o;
        o.x = xv.x * c - xv.y * sn;
        o.y = xv.x * sn + xv.y * c;
        *p = o;
    } else if (idx < QP + KP) {
        int t = idx - QP;
        int i = t & 63;
        int h = (t >> 6) & (NKV - 1);
        int s = t >> 9;
        float c  = fcos[s * 64 + i];
        float sn = fsin[s * 64 + i];
        float2* p = (float2*)(k + (size_t)s * KVD + h * HD + 2 * i);
        float2 xv = *p;
        float2 o;
        o.x = xv.x * c - xv.y * sn;
        o.y = xv.x * sn + xv.y * c;
        *p = o;
    }
}

// ---------------------------------------------------------------------------
// flash attention v2: tf32 mma.sync for QK^T and PV, causal, GQA.
// BM=BN=64, 128 threads = 4 warps; warp owns 16 q-rows.
// Q/K staged row-major [64][132] (tf32); V staged transposed [128][68] (tf32);
// P staged [64][68] (tf32 bits). Online softmax on C-fragment layout.
// ---------------------------------------------------------------------------
#define FQS 132
#define FVS 68
#define Q_OFF 0
#define K_OFF (64*FQS)              // 8448
#define V_OFF (K_OFF + 64*FQS)      // 16896
#define P_OFF (V_OFF + 128*FVS)     // 25600
#define FLASH_SMEM ((P_OFF + 64*FVS)*4)  // 119808 bytes

__global__ __launch_bounds__(128, 1) void flash2(
    const float* __restrict__ q, const float* __restrict__ k,
    const float* __restrict__ v, float* __restrict__ out)
{
    extern __shared__ uint32_t fsm[];
    uint32_t* Qs = fsm + Q_OFF;
    uint32_t* Ks = fsm + K_OFF;
    uint32_t* VT = fsm + V_OFF;
    uint32_t* Ps = fsm + P_OFF;

    const int h   = blockIdx.y;
    const int qb  = gridDim.x - 1 - blockIdx.x;   // big tiles scheduled first
    const int q0  = qb * 64;
    const int kvh = h >> 2;
    const int tid = threadIdx.x;
    const int warp = tid >> 5;
    const int lane = tid & 31;
    const int lg = lane >> 2;
    const int lc = lane & 3;

    // stage Q [64][128] -> tf32
#pragma unroll
    for (int i = 0; i < 16; i++) {
        int idx = i * 128 + tid;
        int row = idx >> 5;
        int c4  = (idx & 31) << 2;
        float4 t = *(const float4*)(q + (size_t)(q0 + row) * DM + h * HD + c4);
        *(uint4*)&Qs[row * FQS + c4] =
            make_uint4(f2tf32(t.x), f2tf32(t.y), f2tf32(t.z), f2tf32(t.w));
    }

    float o[16][4];
#pragma unroll
    for (int ni = 0; ni < 16; ni++)
#pragma unroll
        for (int r = 0; r < 4; r++) o[ni][r] = 0.f;
    float m0 = -3.0e38f, m1 = -3.0e38f, l0 = 0.f, l1 = 0.f;

    const float sc = 0.088388347648318447f;  // 1/sqrt(128)
    const int rowl0 = warp * 16 + lg;        // local q row (c0,c1)

    for (int kb = 0; kb <= qb; kb++) {
        const int k0g = kb * 64;
        // stage K [64][128] tf32 and V transposed [128][64] tf32
#pragma unroll
        for (int i = 0; i < 16; i++) {
            int idx = i * 128 + tid;
            int row = idx >> 5;
            int c4  = (idx & 31) << 2;
            float4 t = *(const float4*)(k + (size_t)(k0g + row) * KVD + kvh * HD + c4);
            *(uint4*)&Ks[row * FQS + c4] =
                make_uint4(f2tf32(t.x), f2tf32(t.y), f2tf32(t.z), f2tf32(t.w));
            float4 u = *(const float4*)(v + (size_t)(k0g + row) * KVD + kvh * HD + c4);
            VT[(c4 + 0) * FVS + row] = f2tf32(u.x);
            VT[(c4 + 1) * FVS + row] = f2tf32(u.y);
            VT[(c4 + 2) * FVS + row] = f2tf32(u.z);
            VT[(c4 + 3) * FVS + row] = f2tf32(u.w);
        }
        __syncthreads();

        // S = Q K^T : warp tile 16x64
        float s[8][4];
#pragma unroll
        for (int ni = 0; ni < 8; ni++)
#pragma unroll
            for (int r = 0; r < 4; r++) s[ni][r] = 0.f;

#pragma unroll
        for (int ks = 0; ks < 16; ks++) {
            const int kk = ks * 8;
            uint32_t qa[4];
            qa[0] = Qs[rowl0 * FQS + kk + lc];
            qa[1] = Qs[(rowl0 + 8) * FQS + kk + lc];
            qa[2] = Qs[rowl0 * FQS + kk + lc + 4];
            qa[3] = Qs[(rowl0 + 8) * FQS + kk + lc + 4];
#pragma unroll
            for (int ni = 0; ni < 8; ni++) {
                uint32_t bfr[2];
                bfr[0] = Ks[(ni * 8 + lg) * FQS + kk + lc];
                bfr[1] = Ks[(ni * 8 + lg) * FQS + kk + lc + 4];
                mma_tf32(s[ni], qa, bfr);
            }
        }

        // scale + causal mask
        const bool diag = (kb == qb);
        float mx0 = -3.0e38f, mx1 = -3.0e38f;
#pragma unroll
        for (int ni = 0; ni < 8; ni++) {
            int cl = ni * 8 + 2 * lc;
#pragma unroll
            for (int j = 0; j < 2; j++) {
                float v0 = s[ni][j] * sc;
                float v1 = s[ni][2 + j] * sc;
                if (diag && (cl + j) > rowl0)     v0 += NEG_BIG;
                if (diag && (cl + j) > rowl0 + 8) v1 += NEG_BIG;
                s[ni][j] = v0; s[ni][2 + j] = v1;
                mx0 = fmaxf(mx0, v0);
                mx1 = fmaxf(mx1, v1);
            }
        }
        mx0 = fmaxf(mx0, __shfl_xor_sync(0xffffffffu, mx0, 1));
        mx0 = fmaxf(mx0, __shfl_xor_sync(0xffffffffu, mx0, 2));
        mx1 = fmaxf(mx1, __shfl_xor_sync(0xffffffffu, mx1, 1));
        mx1 = fmaxf(mx1, __shfl_xor_sync(0xffffffffu, mx1, 2));

        float mn0 = fmaxf(m0, mx0), mn1 = fmaxf(m1, mx1);
        float a0 = __expf(m0 - mn0), a1 = __expf(m1 - mn1);
        m0 = mn0; m1 = mn1;

        float sum0 = 0.f, sum1 = 0.f;
#pragma unroll
        for (int ni = 0; ni < 8; ni++) {
            float p0 = __expf(s[ni][0] - m0);
            float p1 = __expf(s[ni][1] - m0);
            float p2 = __expf(s[ni][2] - m1);
            float p3 = __expf(s[ni][3] - m1);
            sum0 += p0 + p1;
            sum1 += p2 + p3;
            int cl = ni * 8 + 2 * lc;
            *(uint2*)&Ps[rowl0 * FVS + cl]       = make_uint2(f2tf32(p0), f2tf32(p1));
            *(uint2*)&Ps[(rowl0 + 8) * FVS + cl] = make_uint2(f2tf32(p2), f2tf32(p3));
        }
        sum0 += __shfl_xor_sync(0xffffffffu, sum0, 1);
        sum0 += __shfl_xor_sync(0xffffffffu, sum0, 2);
        sum1 += __shfl_xor_sync(0xffffffffu, sum1, 1);
        sum1 += __shfl_xor_sync(0xffffffffu, sum1, 2);
        l0 = l0 * a0 + sum0;
        l1 = l1 * a1 + sum1;

#pragma unroll
        for (int ni = 0; ni < 16; ni++) {
            o[ni][0] *= a0; o[ni][1] *= a0;
            o[ni][2] *= a1; o[ni][3] *= a1;
        }
        __syncwarp();

        // O += P V : warp tile 16x128
#pragma unroll
        for (int ks = 0; ks < 8; ks++) {
            const int kk = ks * 8;
            uint32_t pa[4];
            pa[0] = Ps[rowl0 * FVS + kk + lc];
            pa[1] = Ps[(rowl0 + 8) * FVS + kk + lc];
            pa[2] = Ps[rowl0 * FVS + kk + lc + 4];
            pa[3] = Ps[(rowl0 + 8) * FVS + kk + lc + 4];
#pragma unroll
            for (int ni = 0; ni < 16; ni++) {
                uint32_t bfr[2];
                bfr[0] = VT[(ni * 8 + lg) * FVS + kk + lc];
                bfr[1] = VT[(ni * 8 + lg) * FVS + kk + lc + 4];
                mma_tf32(o[ni], pa, bfr);
            }
        }
        __syncthreads();
    }

    const float inv0 = 1.f / l0, inv1 = 1.f / l1;
    float* ob0 = out + (size_t)(q0 + rowl0) * DM + h * HD;
    float* ob1 = ob0 + (size_t)8 * DM;
#pragma unroll
    for (int ni = 0; ni < 16; ni++) {
        int c = ni * 8 + 2 * lc;
        *(float2*)&ob0[c] = make_float2(o[ni][0] * inv0, o[ni][1] * inv0);
        *(float2*)&ob1[c] = make_float2(o[ni][2] * inv1, o[ni][3] * inv1);
    }
}

// ---------------------------------------------------------------------------
extern "C" void kernel_launch(void* const* d_in, const int* in_sizes, int n_in,
                              void* d_out, int out_size)
{
    const float* x    = (const float*)d_in[0];
    const float* wq   = (const float*)d_in[1];
    const float* wk   = (const float*)d_in[2];
    const float* wv   = (const float*)d_in[3];
    const float* wo   = (const float*)d_in[4];
    const float* fcos = (const float*)d_in[7];
    const float* fsin = (const float*)d_in[8];
    float* out = (float*)d_out;

    float *q, *k, *v, *att;
    cudaGetSymbolAddress((void**)&q,   g_q);
    cudaGetSymbolAddress((void**)&k,   g_k);
    cudaGetSymbolAddress((void**)&v,   g_v);
    cudaGetSymbolAddress((void**)&att, g_att);

    cudaFuncSetAttribute(gemm_mma,
                         cudaFuncAttributeMaxDynamicSharedMemorySize, GEMM_SMEM);
    cudaFuncSetAttribute(flash2,
                         cudaFuncAttributeMaxDynamicSharedMemorySize, FLASH_SMEM);

    // QKV projections (tf32 mma.sync)
    gemm_mma<<<dim3(DM / 128,  SEQ / 128), 128, GEMM_SMEM>>>(x, wq, q, SEQ, DM,  DM);
    gemm_mma<<<dim3(KVD / 128, SEQ / 128), 128, GEMM_SMEM>>>(x, wk, k, SEQ, KVD, DM);
    gemm_mma<<<dim3(KVD / 128, SEQ / 128), 128, GEMM_SMEM>>>(x, wv, v, SEQ, KVD, DM);

    // RoPE
    {
        int total = SEQ * NH * (HD / 2) + SEQ * NKV * (HD / 2);
        rope_kernel<<<(total + 255) / 256, 256>>>(q, k, fcos, fsin);
    }

    // flash attention (tf32 tensor path, no transposes needed)
    flash2<<<dim3(SEQ / 64, NH), 128, FLASH_SMEM>>>(q, k, v, att);

    // output projection
    gemm_mma<<<dim3(DM / 128, SEQ / 128), 128, GEMM_SMEM>>>(att, wo, out, SEQ, DM, DM);
}

// round 5
// speedup vs baseline: 7.6086x; 3.5847x over previous
#include <cuda_runtime.h>
#include <cuda_fp16.h>
#include <cstdint>

#define SEQ 2048
#define DM  4096
#define NH  32
#define NKV 8
#define HD  128
#define KVD (NKV*HD)
#define NEG_BIG -1.0e9f

// half scratch buffers (static device globals)
__device__ __half g_xh [SEQ*DM];
__device__ __half g_wqh[DM*DM];
__device__ __half g_wkh[KVD*DM];
__device__ __half g_wvh[KVD*DM];
__device__ __half g_woh[DM*DM];
__device__ __half g_qh [SEQ*DM];
__device__ __half g_kh [SEQ*KVD];
__device__ __half g_vh [SEQ*KVD];
__device__ __half g_ath[SEQ*DM];

// ---------------------------------------------------------------------------
// helpers
// ---------------------------------------------------------------------------
__device__ __forceinline__ uint32_t smem_u32(const void* p) {
    uint32_t a;
    asm("{ .reg .u64 t; cvta.to.shared.u64 t, %1; cvt.u32.u64 %0, t; }"
        : "=r"(a) : "l"(p));
    return a;
}
__device__ __forceinline__ uint32_t h2pack(float a, float b) {
    __half2 h = __floats2half2_rn(a, b);
    return *reinterpret_cast<uint32_t*>(&h);
}
__device__ __forceinline__ void cpa16(uint32_t dst, const void* src) {
    asm volatile("cp.async.cg.shared.global [%0], [%1], 16;"
                 :: "r"(dst), "l"(src));
}
__device__ __forceinline__ void cp_commit() {
    asm volatile("cp.async.commit_group;" ::: "memory");
}
__device__ __forceinline__ void ldsm4(uint32_t* r, uint32_t addr) {
    asm volatile("ldmatrix.sync.aligned.m8n8.x4.shared.b16 {%0,%1,%2,%3}, [%4];"
                 : "=r"(r[0]), "=r"(r[1]), "=r"(r[2]), "=r"(r[3]) : "r"(addr));
}
__device__ __forceinline__ void ldsm4t(uint32_t* r, uint32_t addr) {
    asm volatile("ldmatrix.sync.aligned.m8n8.x4.trans.shared.b16 {%0,%1,%2,%3}, [%4];"
                 : "=r"(r[0]), "=r"(r[1]), "=r"(r[2]), "=r"(r[3]) : "r"(addr));
}
__device__ __forceinline__ void mma_f16(float* d, const uint32_t* a,
                                        const uint32_t* b) {
    asm volatile(
        "mma.sync.aligned.m16n8k16.row.col.f32.f16.f16.f32 "
        "{%0,%1,%2,%3},{%4,%5,%6,%7},{%8,%9},{%0,%1,%2,%3};"
        : "+f"(d[0]), "+f"(d[1]), "+f"(d[2]), "+f"(d[3])
        : "r"(a[0]), "r"(a[1]), "r"(a[2]), "r"(a[3]), "r"(b[0]), "r"(b[1]));
}

// ---------------------------------------------------------------------------
// fp32 -> fp16 bulk convert (vectorized, n % 4 == 0)
// ---------------------------------------------------------------------------
__global__ void f2h_kernel(const float* __restrict__ in,
                           __half* __restrict__ out, int n)
{
    int i = (blockIdx.x * blockDim.x + threadIdx.x) * 4;
    if (i < n) {
        float4 v = *(const float4*)(in + i);
        *(uint2*)(out + i) = make_uint2(h2pack(v.x, v.y), h2pack(v.z, v.w));
    }
}

// ---------------------------------------------------------------------------
// fp16 mma GEMM: C[M,N] = A[M,K] * B[N,K]^T  (half row-major, K contiguous)
// CTA 128x128, kc=32, 256 thr = 8 warps (2Mx4N), warp tile 64x32,
// cp.async 3-stage pipeline, ldmatrix fragments, padded stride 40 halves.
// ---------------------------------------------------------------------------
#define GSTW 5120                 // words per stage (A 2560 + B 2560)
#define GEMM_SMEM (3*GSTW*4)      // 61440 B

template<bool HOUT>
__global__ __launch_bounds__(256, 2) void gemm_h(
    const __half* __restrict__ A, const __half* __restrict__ B,
    void* __restrict__ Cv, int M, int N, int K)
{
    extern __shared__ uint32_t smq[];
    const uint32_t sb = smem_u32(smq);

    const int tid  = threadIdx.x;
    const int lane = tid & 31;
    const int warp = tid >> 5;
    const int wm = warp & 1, wn = warp >> 1;
    const int l7 = lane & 7, l8 = (lane >> 3) & 1, l16 = lane >> 4;
    const int lg = lane >> 2, lc = lane & 3;

    // cp.async loader mapping: thread -> (rows r0, r0+64), 16B chunk c0
    const int r0 = tid >> 2, c0 = tid & 3;
    const __half* Ab  = A + (size_t)(blockIdx.y * 128 + r0) * K + c0 * 8;
    const __half* Ab2 = Ab + (size_t)64 * K;
    const __half* Bb  = B + (size_t)(blockIdx.x * 128 + r0) * K + c0 * 8;
    const __half* Bb2 = Bb + (size_t)64 * K;
    const uint32_t dA1 = (uint32_t)(r0 * 20 + c0 * 4) * 4;
    const uint32_t dA2 = (uint32_t)((r0 + 64) * 20 + c0 * 4) * 4;
    const uint32_t dB1 = dA1 + 2560 * 4;
    const uint32_t dB2 = dA2 + 2560 * 4;

    // fragment lane offsets (bytes, relative to stage base)
    const uint32_t aoff = (uint32_t)((wm * 64 + l7 + 8 * l8) * 20 + 4 * l16) * 4;
    const uint32_t boff = (uint32_t)(2560 + (wn * 32 + l7 + 8 * l16) * 20 + 4 * l8) * 4;

    float acc[4][4][4];
#pragma unroll
    for (int mi = 0; mi < 4; mi++)
#pragma unroll
        for (int ni = 0; ni < 4; ni++)
#pragma unroll
            for (int r = 0; r < 4; r++) acc[mi][ni][r] = 0.f;

    const int kiters = K / 32;
    // prologue: stages 0 and 1
#pragma unroll
    for (int p = 0; p < 2; p++) {
        uint32_t base = sb + p * GSTW * 4;
        int koff = p * 32;
        cpa16(base + dA1, Ab + koff);
        cpa16(base + dA2, Ab2 + koff);
        cpa16(base + dB1, Bb + koff);
        cpa16(base + dB2, Bb2 + koff);
        cp_commit();
    }

    int st = 0;
    for (int kt = 0; kt < kiters; kt++) {
        if (kt + 1 < kiters)
            asm volatile("cp.async.wait_group 1;" ::: "memory");
        else
            asm volatile("cp.async.wait_group 0;" ::: "memory");
        __syncthreads();

        if (kt + 2 < kiters) {
            int s2 = st + 2; if (s2 >= 3) s2 -= 3;
            uint32_t base = sb + s2 * GSTW * 4;
            int koff = (kt + 2) * 32;
            cpa16(base + dA1, Ab + koff);
            cpa16(base + dA2, Ab2 + koff);
            cpa16(base + dB1, Bb + koff);
            cpa16(base + dB2, Bb2 + koff);
            cp_commit();
        }

        const uint32_t sbase = sb + st * GSTW * 4;
#pragma unroll
        for (int ks = 0; ks < 2; ks++) {
            uint32_t af[4][4];
#pragma unroll
            for (int mi = 0; mi < 4; mi++)
                ldsm4(af[mi], sbase + aoff + mi * 1280 + ks * 32);
            uint32_t bf0[4], bf1[4];
            ldsm4(bf0, sbase + boff + ks * 32);
            ldsm4(bf1, sbase + boff + 1280 + ks * 32);
#pragma unroll
            for (int mi = 0; mi < 4; mi++) {
                mma_f16(acc[mi][0], af[mi], bf0);
                mma_f16(acc[mi][1], af[mi], bf0 + 2);
                mma_f16(acc[mi][2], af[mi], bf1);
                mma_f16(acc[mi][3], af[mi], bf1 + 2);
            }
        }
        if (++st == 3) st = 0;
    }

    // epilogue
#pragma unroll
    for (int mi = 0; mi < 4; mi++) {
        int r = blockIdx.y * 128 + wm * 64 + mi * 16 + lg;
#pragma unroll
        for (int ni = 0; ni < 4; ni++) {
            int c = blockIdx.x * 128 + wn * 32 + ni * 8 + lc * 2;
            if (HOUT) {
                __half* C = (__half*)Cv;
                *(uint32_t*)&C[(size_t)r * N + c] =
                    h2pack(acc[mi][ni][0], acc[mi][ni][1]);
                *(uint32_t*)&C[(size_t)(r + 8) * N + c] =
                    h2pack(acc[mi][ni][2], acc[mi][ni][3]);
            } else {
                float* C = (float*)Cv;
                *(float2*)&C[(size_t)r * N + c] =
                    make_float2(acc[mi][ni][0], acc[mi][ni][1]);
                *(float2*)&C[(size_t)(r + 8) * N + c] =
                    make_float2(acc[mi][ni][2], acc[mi][ni][3]);
            }
        }
    }
}

// ---------------------------------------------------------------------------
// RoPE in-place on half q [SEQ][NH][HD], k [SEQ][NKV][HD]
// ---------------------------------------------------------------------------
__global__ void rope_h(__half* __restrict__ q, __half* __restrict__ k,
                       const float* __restrict__ fcos,
                       const float* __restrict__ fsin)
{
    const int QP = SEQ * NH  * (HD / 2);
    const int KP = SEQ * NKV * (HD / 2);
    int idx = blockIdx.x * blockDim.x + threadIdx.x;
    if (idx < QP) {
        int i = idx & 63;
        int h = (idx >> 6) & (NH - 1);
        int s = idx >> 11;
        float c  = fcos[s * 64 + i];
        float sn = fsin[s * 64 + i];
        __half2* p = (__half2*)(q + (size_t)s * DM + h * HD + 2 * i);
        float2 xv = __half22float2(*p);
        *p = __floats2half2_rn(xv.x * c - xv.y * sn, xv.x * sn + xv.y * c);
    } else if (idx < QP + KP) {
        int t = idx - QP;
        int i = t & 63;
        int h = (t >> 6) & (NKV - 1);
        int s = t >> 9;
        float c  = fcos[s * 64 + i];
        float sn = fsin[s * 64 + i];
        __half2* p = (__half2*)(k + (size_t)s * KVD + h * HD + 2 * i);
        float2 xv = __half22float2(*p);
        *p = __floats2half2_rn(xv.x * c - xv.y * sn, xv.x * sn + xv.y * c);
    }
}

// ---------------------------------------------------------------------------
// flash attention v3: fp16 mma, P-in-registers, cp.async double-buffered K/V.
// BM=BN=64, 128 thr = 4 warps, warp owns 16 q rows. Causal, GQA.
// smem: Q[64][136h] + K[2][64][136h] + V[2][64][136h]  (stride 68 words)
// ---------------------------------------------------------------------------
#define FTW 4352                    // words per 64x136h tile
#define FLASH_SMEM (5*FTW*4)        // 87040 B

__global__ __launch_bounds__(128, 2) void flash_h(
    const __half* __restrict__ q, const __half* __restrict__ k,
    const __half* __restrict__ v, __half* __restrict__ outh)
{
    extern __shared__ uint32_t fsm[];
    const uint32_t sb = smem_u32(fsm);

    const int h   = blockIdx.y;
    const int qb  = gridDim.x - 1 - blockIdx.x;
    const int q0  = qb * 64;
    const int kvh = h >> 2;
    const int tid = threadIdx.x;
    const int warp = tid >> 5;
    const int lane = tid & 31;
    const int l7 = lane & 7, l8 = (lane >> 3) & 1, l16 = lane >> 4;
    const int lg = lane >> 2, lc = lane & 3;

    // cp.async loader mapping: c chunk fixed, rows rb + 8i
    const int rb = tid >> 4, cch = tid & 15;

    // stage Q + tile 0 as one group
#pragma unroll
    for (int i = 0; i < 8; i++) {
        int r = i * 8 + rb;
        cpa16(sb + (uint32_t)(r * 68 + cch * 4) * 4,
              q + (size_t)(q0 + r) * DM + h * HD + cch * 8);
    }
    {
        const int k0g = 0;
#pragma unroll
        for (int i = 0; i < 8; i++) {
            int r = i * 8 + rb;
            const __half* src = k + (size_t)(k0g + r) * KVD + kvh * HD + cch * 8;
            const __half* srcv = v + (size_t)(k0g + r) * KVD + kvh * HD + cch * 8;
            cpa16(sb + (uint32_t)(FTW + r * 68 + cch * 4) * 4, src);
            cpa16(sb + (uint32_t)(3 * FTW + r * 68 + cch * 4) * 4, srcv);
        }
        cp_commit();
    }

    // fragment lane offsets (bytes)
    const uint32_t Qa = (uint32_t)((warp * 16 + l7 + 8 * l8) * 68 + 4 * l16) * 4;
    const uint32_t Kb = (uint32_t)((l7 + 8 * l16) * 68 + 4 * l8) * 4;
    const uint32_t Vb = (uint32_t)((l7 + 8 * l8) * 68 + 4 * l16) * 4;

    float o[16][4];
#pragma unroll
    for (int ni = 0; ni < 16; ni++)
#pragma unroll
        for (int r = 0; r < 4; r++) o[ni][r] = 0.f;
    float m0 = -3.0e38f, m1 = -3.0e38f, l0 = 0.f, l1 = 0.f;

    const float sc = 0.088388347648318447f;   // 1/sqrt(128)
    const int rowl0 = warp * 16 + lg;

    for (int kb = 0; kb <= qb; kb++) {
        asm volatile("cp.async.wait_group 0;" ::: "memory");
        __syncthreads();

        if (kb + 1 <= qb) {
            const int k0n = (kb + 1) * 64;
            const uint32_t bufn = (uint32_t)((kb + 1) & 1) * FTW;
#pragma unroll
            for (int i = 0; i < 8; i++) {
                int r = i * 8 + rb;
                const __half* src  = k + (size_t)(k0n + r) * KVD + kvh * HD + cch * 8;
                const __half* srcv = v + (size_t)(k0n + r) * KVD + kvh * HD + cch * 8;
                cpa16(sb + ((FTW + bufn) + (uint32_t)(r * 68 + cch * 4)) * 4, src);
                cpa16(sb + ((3 * FTW + bufn) + (uint32_t)(r * 68 + cch * 4)) * 4, srcv);
            }
            cp_commit();
        }

        const uint32_t bufK = sb + (FTW + (uint32_t)(kb & 1) * FTW) * 4;
        const uint32_t bufV = sb + (3 * FTW + (uint32_t)(kb & 1) * FTW) * 4;

        // S = Q K^T (warp tile 16x64)
        float s[8][4];
#pragma unroll
        for (int ni = 0; ni < 8; ni++)
#pragma unroll
            for (int r = 0; r < 4; r++) s[ni][r] = 0.f;

#pragma unroll
        for (int kd = 0; kd < 8; kd++) {
            uint32_t qa[4];
            ldsm4(qa, sb + Qa + kd * 32);
#pragma unroll
            for (int nj = 0; nj < 4; nj++) {
                uint32_t kb4[4];
                ldsm4(kb4, bufK + Kb + nj * 4352 + kd * 32);
                mma_f16(s[2 * nj],     qa, kb4);
                mma_f16(s[2 * nj + 1], qa, kb4 + 2);
            }
        }

        // scale + causal mask + online softmax
        const bool diag = (kb == qb);
        float mx0 = -3.0e38f, mx1 = -3.0e38f;
#pragma unroll
        for (int ni = 0; ni < 8; ni++) {
            int cl = ni * 8 + 2 * lc;
#pragma unroll
            for (int j = 0; j < 2; j++) {
                float v0 = s[ni][j] * sc;
                float v1 = s[ni][2 + j] * sc;
                if (diag && (cl + j) > rowl0)     v0 += NEG_BIG;
                if (diag && (cl + j) > rowl0 + 8) v1 += NEG_BIG;
                s[ni][j] = v0; s[ni][2 + j] = v1;
                mx0 = fmaxf(mx0, v0);
                mx1 = fmaxf(mx1, v1);
            }
        }
        mx0 = fmaxf(mx0, __shfl_xor_sync(0xffffffffu, mx0, 1));
        mx0 = fmaxf(mx0, __shfl_xor_sync(0xffffffffu, mx0, 2));
        mx1 = fmaxf(mx1, __shfl_xor_sync(0xffffffffu, mx1, 1));
        mx1 = fmaxf(mx1, __shfl_xor_sync(0xffffffffu, mx1, 2));

        float mn0 = fmaxf(m0, mx0), mn1 = fmaxf(m1, mx1);
        float a0 = __expf(m0 - mn0), a1 = __expf(m1 - mn1);
        m0 = mn0; m1 = mn1;

        float sum0 = 0.f, sum1 = 0.f;
#pragma unroll
        for (int ni = 0; ni < 8; ni++) {
            float p0 = __expf(s[ni][0] - m0);
            float p1 = __expf(s[ni][1] - m0);
            float p2 = __expf(s[ni][2] - m1);
            float p3 = __expf(s[ni][3] - m1);
            s[ni][0] = p0; s[ni][1] = p1; s[ni][2] = p2; s[ni][3] = p3;
            sum0 += p0 + p1;
            sum1 += p2 + p3;
        }
        sum0 += __shfl_xor_sync(0xffffffffu, sum0, 1);
        sum0 += __shfl_xor_sync(0xffffffffu, sum0, 2);
        sum1 += __shfl_xor_sync(0xffffffffu, sum1, 1);
        sum1 += __shfl_xor_sync(0xffffffffu, sum1, 2);
        l0 = l0 * a0 + sum0;
        l1 = l1 * a1 + sum1;

#pragma unroll
        for (int ni = 0; ni < 16; ni++) {
            o[ni][0] *= a0; o[ni][1] *= a0;
            o[ni][2] *= a1; o[ni][3] *= a1;
        }

        // O += P V : P fragments straight from registers
#pragma unroll
        for (int ks = 0; ks < 4; ks++) {
            uint32_t pa[4];
            pa[0] = h2pack(s[2 * ks][0],     s[2 * ks][1]);
            pa[1] = h2pack(s[2 * ks][2],     s[2 * ks][3]);
            pa[2] = h2pack(s[2 * ks + 1][0], s[2 * ks + 1][1]);
            pa[3] = h2pack(s[2 * ks + 1][2], s[2 * ks + 1][3]);
#pragma unroll
            for (int dj = 0; dj < 8; dj++) {
                uint32_t vb4[4];
                ldsm4t(vb4, bufV + Vb + ks * 4352 + dj * 32);
                mma_f16(o[2 * dj],     pa, vb4);
                mma_f16(o[2 * dj + 1], pa, vb4 + 2);
            }
        }
    }

    const float inv0 = 1.f / l0, inv1 = 1.f / l1;
    __half* ob0 = outh + (size_t)(q0 + rowl0) * DM + h * HD;
    __half* ob1 = ob0 + (size_t)8 * DM;
#pragma unroll
    for (int ni = 0; ni < 16; ni++) {
        int c = ni * 8 + 2 * lc;
        *(uint32_t*)&ob0[c] = h2pack(o[ni][0] * inv0, o[ni][1] * inv0);
        *(uint32_t*)&ob1[c] = h2pack(o[ni][2] * inv1, o[ni][3] * inv1);
    }
}

// ---------------------------------------------------------------------------
extern "C" void kernel_launch(void* const* d_in, const int* in_sizes, int n_in,
                              void* d_out, int out_size)
{
    const float* x    = (const float*)d_in[0];
    const float* wq   = (const float*)d_in[1];
    const float* wk   = (const float*)d_in[2];
    const float* wv   = (const float*)d_in[3];
    const float* wo   = (const float*)d_in[4];
    const float* fcos = (const float*)d_in[7];
    const float* fsin = (const float*)d_in[8];
    float* out = (float*)d_out;

    __half *xh, *wqh, *wkh, *wvh, *woh, *qh, *kh, *vh, *ath;
    cudaGetSymbolAddress((void**)&xh,  g_xh);
    cudaGetSymbolAddress((void**)&wqh, g_wqh);
    cudaGetSymbolAddress((void**)&wkh, g_wkh);
    cudaGetSymbolAddress((void**)&wvh, g_wvh);
    cudaGetSymbolAddress((void**)&woh, g_woh);
    cudaGetSymbolAddress((void**)&qh,  g_qh);
    cudaGetSymbolAddress((void**)&kh,  g_kh);
    cudaGetSymbolAddress((void**)&vh,  g_vh);
    cudaGetSymbolAddress((void**)&ath, g_ath);

    cudaFuncSetAttribute(gemm_h<true>,
                         cudaFuncAttributeMaxDynamicSharedMemorySize, GEMM_SMEM);
    cudaFuncSetAttribute(gemm_h<false>,
                         cudaFuncAttributeMaxDynamicSharedMemorySize, GEMM_SMEM);
    cudaFuncSetAttribute(flash_h,
                         cudaFuncAttributeMaxDynamicSharedMemorySize, FLASH_SMEM);

    // convert inputs to half
    auto cvt = [](const float* s, __half* d, int n) {
        f2h_kernel<<<(n / 4 + 255) / 256, 256>>>(s, d, n);
    };
    cvt(x,  xh,  SEQ * DM);
    cvt(wq, wqh, DM * DM);
    cvt(wk, wkh, KVD * DM);
    cvt(wv, wvh, KVD * DM);
    cvt(wo, woh, DM * DM);

    // QKV projections (half in, half out)
    gemm_h<true><<<dim3(DM / 128,  SEQ / 128), 256, GEMM_SMEM>>>(xh, wqh, qh, SEQ, DM,  DM);
    gemm_h<true><<<dim3(KVD / 128, SEQ / 128), 256, GEMM_SMEM>>>(xh, wkh, kh, SEQ, KVD, DM);
    gemm_h<true><<<dim3(KVD / 128, SEQ / 128), 256, GEMM_SMEM>>>(xh, wvh, vh, SEQ, KVD, DM);

    // RoPE on half q/k
    {
        int total = SEQ * NH * (HD / 2) + SEQ * NKV * (HD / 2);
        rope_h<<<(total + 255) / 256, 256>>>(qh, kh, fcos, fsin);
    }

    // flash attention (fp16 tensor path), writes half att
    flash_h<<<dim3(SEQ / 64, NH), 128, FLASH_SMEM>>>(qh, kh, vh, ath);

    // output projection (half in, float out)
    gemm_h<false><<<dim3(DM / 128, SEQ / 128), 256, GEMM_SMEM>>>(ath, woh, out, SEQ, DM, DM);
}

// round 6
// speedup vs baseline: 8.0344x; 1.0560x over previous
#include <cuda_runtime.h>
#include <cuda_fp16.h>
#include <cstdint>

#define SEQ 2048
#define DM  4096
#define NH  32
#define NKV 8
#define HD  128
#define KVD (NKV*HD)
#define NEG_BIG -1.0e9f

// half scratch buffers (static device globals)
__device__ __half g_xh [SEQ*DM];
__device__ __half g_wqh[DM*DM];
__device__ __half g_wkh[KVD*DM];
__device__ __half g_wvh[KVD*DM];
__device__ __half g_woh[DM*DM];
__device__ __half g_qh [SEQ*DM];
__device__ __half g_kh [SEQ*KVD];
__device__ __half g_vh [SEQ*KVD];
__device__ __half g_ath[SEQ*DM];

// ---------------------------------------------------------------------------
// helpers
// ---------------------------------------------------------------------------
__device__ __forceinline__ uint32_t smem_u32(const void* p) {
    uint32_t a;
    asm("{ .reg .u64 t; cvta.to.shared.u64 t, %1; cvt.u32.u64 %0, t; }"
        : "=r"(a) : "l"(p));
    return a;
}
__device__ __forceinline__ uint32_t h2pack(float a, float b) {
    __half2 h = __floats2half2_rn(a, b);
    return *reinterpret_cast<uint32_t*>(&h);
}
__device__ __forceinline__ void cpa16(uint32_t dst, const void* src) {
    asm volatile("cp.async.cg.shared.global [%0], [%1], 16;"
                 :: "r"(dst), "l"(src));
}
__device__ __forceinline__ void cp_commit() {
    asm volatile("cp.async.commit_group;" ::: "memory");
}
__device__ __forceinline__ void ldsm4(uint32_t* r, uint32_t addr) {
    asm volatile("ldmatrix.sync.aligned.m8n8.x4.shared.b16 {%0,%1,%2,%3}, [%4];"
                 : "=r"(r[0]), "=r"(r[1]), "=r"(r[2]), "=r"(r[3]) : "r"(addr));
}
__device__ __forceinline__ void ldsm4t(uint32_t* r, uint32_t addr) {
    asm volatile("ldmatrix.sync.aligned.m8n8.x4.trans.shared.b16 {%0,%1,%2,%3}, [%4];"
                 : "=r"(r[0]), "=r"(r[1]), "=r"(r[2]), "=r"(r[3]) : "r"(addr));
}
__device__ __forceinline__ void mma_f16(float* d, const uint32_t* a,
                                        const uint32_t* b) {
    asm volatile(
        "mma.sync.aligned.m16n8k16.row.col.f32.f16.f16.f32 "
        "{%0,%1,%2,%3},{%4,%5,%6,%7},{%8,%9},{%0,%1,%2,%3};"
        : "+f"(d[0]), "+f"(d[1]), "+f"(d[2]), "+f"(d[3])
        : "r"(a[0]), "r"(a[1]), "r"(a[2]), "r"(a[3]), "r"(b[0]), "r"(b[1]));
}

// ---------------------------------------------------------------------------
// fused fp32 -> fp16 convert of all five tensors (one launch)
// ---------------------------------------------------------------------------
#define F4_X  2097152   // SEQ*DM/4
#define F4_WQ 4194304   // DM*DM/4
#define F4_KV 1048576   // KVD*DM/4
#define F4_C0 (F4_X)
#define F4_C1 (F4_C0 + F4_WQ)
#define F4_C2 (F4_C1 + F4_KV)
#define F4_C3 (F4_C2 + F4_KV)
#define F4_C4 (F4_C3 + F4_WQ)

__global__ void f2h_all(const float* __restrict__ x,  const float* __restrict__ wq,
                        const float* __restrict__ wk, const float* __restrict__ wv,
                        const float* __restrict__ wo,
                        __half* xh, __half* wqh, __half* wkh, __half* wvh, __half* woh)
{
    int i = blockIdx.x * blockDim.x + threadIdx.x;
    const float* s;
    __half* d;
    int off;
    if (i < F4_C0)      { s = x;  d = xh;  off = i; }
    else if (i < F4_C1) { s = wq; d = wqh; off = i - F4_C0; }
    else if (i < F4_C2) { s = wk; d = wkh; off = i - F4_C1; }
    else if (i < F4_C3) { s = wv; d = wvh; off = i - F4_C2; }
    else if (i < F4_C4) { s = wo; d = woh; off = i - F4_C3; }
    else return;
    float4 v = *(const float4*)(s + (size_t)off * 4);
    *(uint2*)(d + (size_t)off * 4) = make_uint2(h2pack(v.x, v.y), h2pack(v.z, v.w));
}

// ---------------------------------------------------------------------------
// GEMM core macros (CTA 128x128, kc=32, 256 thr, 8 warps 2Mx4N, warp 64x32,
// cp.async 3-stage, ldmatrix, padded stride 40 halves)
// ---------------------------------------------------------------------------
#define GSTW 5120                 // words per stage (A 2560 + B 2560)
#define GEMM_SMEM (3*GSTW*4)      // 61440 B

// fused QKV: one launch; blockIdx.x selects Q (0..31), K (32..39), V (40..47)
__global__ __launch_bounds__(256, 2) void qkv_gemm(
    const __half* __restrict__ Aq,
    const __half* __restrict__ wq, const __half* __restrict__ wk,
    const __half* __restrict__ wv,
    __half* __restrict__ qo, __half* __restrict__ ko, __half* __restrict__ vo)
{
    extern __shared__ uint32_t smq[];
    const uint32_t sb = smem_u32(smq);
    const int K = DM;

    int bx = blockIdx.x;
    const __half* Bsel;
    __half* Csel;
    int Nc, cb;
    if (bx < 32)      { Bsel = wq; Csel = qo; Nc = DM;  cb = bx; }
    else if (bx < 40) { Bsel = wk; Csel = ko; Nc = KVD; cb = bx - 32; }
    else              { Bsel = wv; Csel = vo; Nc = KVD; cb = bx - 40; }

    const int tid  = threadIdx.x;
    const int lane = tid & 31;
    const int warp = tid >> 5;
    const int wm = warp & 1, wn = warp >> 1;
    const int l7 = lane & 7, l8 = (lane >> 3) & 1, l16 = lane >> 4;
    const int lg = lane >> 2, lc = lane & 3;

    const int r0 = tid >> 2, c0 = tid & 3;
    const __half* Ab  = Aq + (size_t)(blockIdx.y * 128 + r0) * K + c0 * 8;
    const __half* Ab2 = Ab + (size_t)64 * K;
    const __half* Bb  = Bsel + (size_t)(cb * 128 + r0) * K + c0 * 8;
    const __half* Bb2 = Bb + (size_t)64 * K;
    const uint32_t dA1 = (uint32_t)(r0 * 20 + c0 * 4) * 4;
    const uint32_t dA2 = (uint32_t)((r0 + 64) * 20 + c0 * 4) * 4;
    const uint32_t dB1 = dA1 + 2560 * 4;
    const uint32_t dB2 = dA2 + 2560 * 4;

    const uint32_t aoff = (uint32_t)((wm * 64 + l7 + 8 * l8) * 20 + 4 * l16) * 4;
    const uint32_t boff = (uint32_t)(2560 + (wn * 32 + l7 + 8 * l16) * 20 + 4 * l8) * 4;

    float acc[4][4][4];
#pragma unroll
    for (int mi = 0; mi < 4; mi++)
#pragma unroll
        for (int ni = 0; ni < 4; ni++)
#pragma unroll
            for (int r = 0; r < 4; r++) acc[mi][ni][r] = 0.f;

    const int kiters = K / 32;
#pragma unroll
    for (int p = 0; p < 2; p++) {
        uint32_t base = sb + p * GSTW * 4;
        int koff = p * 32;
        cpa16(base + dA1, Ab + koff);
        cpa16(base + dA2, Ab2 + koff);
        cpa16(base + dB1, Bb + koff);
        cpa16(base + dB2, Bb2 + koff);
        cp_commit();
    }

    int st = 0;
    for (int kt = 0; kt < kiters; kt++) {
        if (kt + 1 < kiters)
            asm volatile("cp.async.wait_group 1;" ::: "memory");
        else
            asm volatile("cp.async.wait_group 0;" ::: "memory");
        __syncthreads();

        if (kt + 2 < kiters) {
            int s2 = st + 2; if (s2 >= 3) s2 -= 3;
            uint32_t base = sb + s2 * GSTW * 4;
            int koff = (kt + 2) * 32;
            cpa16(base + dA1, Ab + koff);
            cpa16(base + dA2, Ab2 + koff);
            cpa16(base + dB1, Bb + koff);
            cpa16(base + dB2, Bb2 + koff);
            cp_commit();
        }

        const uint32_t sbase = sb + st * GSTW * 4;
#pragma unroll
        for (int ks = 0; ks < 2; ks++) {
            uint32_t af[4][4];
#pragma unroll
            for (int mi = 0; mi < 4; mi++)
                ldsm4(af[mi], sbase + aoff + mi * 1280 + ks * 32);
            uint32_t bf0[4], bf1[4];
            ldsm4(bf0, sbase + boff + ks * 32);
            ldsm4(bf1, sbase + boff + 1280 + ks * 32);
#pragma unroll
            for (int mi = 0; mi < 4; mi++) {
                mma_f16(acc[mi][0], af[mi], bf0);
                mma_f16(acc[mi][1], af[mi], bf0 + 2);
                mma_f16(acc[mi][2], af[mi], bf1);
                mma_f16(acc[mi][3], af[mi], bf1 + 2);
            }
        }
        if (++st == 3) st = 0;
    }

#pragma unroll
    for (int mi = 0; mi < 4; mi++) {
        int r = blockIdx.y * 128 + wm * 64 + mi * 16 + lg;
#pragma unroll
        for (int ni = 0; ni < 4; ni++) {
            int c = cb * 128 + wn * 32 + ni * 8 + lc * 2;
            *(uint32_t*)&Csel[(size_t)r * Nc + c] =
                h2pack(acc[mi][ni][0], acc[mi][ni][1]);
            *(uint32_t*)&Csel[(size_t)(r + 8) * Nc + c] =
                h2pack(acc[mi][ni][2], acc[mi][ni][3]);
        }
    }
}

// O-projection: half in, float out
__global__ __launch_bounds__(256, 2) void gemm_of(
    const __half* __restrict__ A, const __half* __restrict__ B,
    float* __restrict__ C, int M, int N, int K)
{
    extern __shared__ uint32_t smq[];
    const uint32_t sb = smem_u32(smq);

    const int tid  = threadIdx.x;
    const int lane = tid & 31;
    const int warp = tid >> 5;
    const int wm = warp & 1, wn = warp >> 1;
    const int l7 = lane & 7, l8 = (lane >> 3) & 1, l16 = lane >> 4;
    const int lg = lane >> 2, lc = lane & 3;

    const int r0 = tid >> 2, c0 = tid & 3;
    const __half* Ab  = A + (size_t)(blockIdx.y * 128 + r0) * K + c0 * 8;
    const __half* Ab2 = Ab + (size_t)64 * K;
    const __half* Bb  = B + (size_t)(blockIdx.x * 128 + r0) * K + c0 * 8;
    const __half* Bb2 = Bb + (size_t)64 * K;
    const uint32_t dA1 = (uint32_t)(r0 * 20 + c0 * 4) * 4;
    const uint32_t dA2 = (uint32_t)((r0 + 64) * 20 + c0 * 4) * 4;
    const uint32_t dB1 = dA1 + 2560 * 4;
    const uint32_t dB2 = dA2 + 2560 * 4;

    const uint32_t aoff = (uint32_t)((wm * 64 + l7 + 8 * l8) * 20 + 4 * l16) * 4;
    const uint32_t boff = (uint32_t)(2560 + (wn * 32 + l7 + 8 * l16) * 20 + 4 * l8) * 4;

    float acc[4][4][4];
#pragma unroll
    for (int mi = 0; mi < 4; mi++)
#pragma unroll
        for (int ni = 0; ni < 4; ni++)
#pragma unroll
            for (int r = 0; r < 4; r++) acc[mi][ni][r] = 0.f;

    const int kiters = K / 32;
#pragma unroll
    for (int p = 0; p < 2; p++) {
        uint32_t base = sb + p * GSTW * 4;
        int koff = p * 32;
        cpa16(base + dA1, Ab + koff);
        cpa16(base + dA2, Ab2 + koff);
        cpa16(base + dB1, Bb + koff);
        cpa16(base + dB2, Bb2 + koff);
        cp_commit();
    }

    int st = 0;
    for (int kt = 0; kt < kiters; kt++) {
        if (kt + 1 < kiters)
            asm volatile("cp.async.wait_group 1;" ::: "memory");
        else
            asm volatile("cp.async.wait_group 0;" ::: "memory");
        __syncthreads();

        if (kt + 2 < kiters) {
            int s2 = st + 2; if (s2 >= 3) s2 -= 3;
            uint32_t base = sb + s2 * GSTW * 4;
            int koff = (kt + 2) * 32;
            cpa16(base + dA1, Ab + koff);
            cpa16(base + dA2, Ab2 + koff);
            cpa16(base + dB1, Bb + koff);
            cpa16(base + dB2, Bb2 + koff);
            cp_commit();
        }

        const uint32_t sbase = sb + st * GSTW * 4;
#pragma unroll
        for (int ks = 0; ks < 2; ks++) {
            uint32_t af[4][4];
#pragma unroll
            for (int mi = 0; mi < 4; mi++)
                ldsm4(af[mi], sbase + aoff + mi * 1280 + ks * 32);
            uint32_t bf0[4], bf1[4];
            ldsm4(bf0, sbase + boff + ks * 32);
            ldsm4(bf1, sbase + boff + 1280 + ks * 32);
#pragma unroll
            for (int mi = 0; mi < 4; mi++) {
                mma_f16(acc[mi][0], af[mi], bf0);
                mma_f16(acc[mi][1], af[mi], bf0 + 2);
                mma_f16(acc[mi][2], af[mi], bf1);
                mma_f16(acc[mi][3], af[mi], bf1 + 2);
            }
        }
        if (++st == 3) st = 0;
    }

#pragma unroll
    for (int mi = 0; mi < 4; mi++) {
        int r = blockIdx.y * 128 + wm * 64 + mi * 16 + lg;
#pragma unroll
        for (int ni = 0; ni < 4; ni++) {
            int c = blockIdx.x * 128 + wn * 32 + ni * 8 + lc * 2;
            *(float2*)&C[(size_t)r * N + c] =
                make_float2(acc[mi][ni][0], acc[mi][ni][1]);
            *(float2*)&C[(size_t)(r + 8) * N + c] =
                make_float2(acc[mi][ni][2], acc[mi][ni][3]);
        }
    }
}

// ---------------------------------------------------------------------------
// RoPE in-place on half q [SEQ][NH][HD], k [SEQ][NKV][HD]
// ---------------------------------------------------------------------------
__global__ void rope_h(__half* __restrict__ q, __half* __restrict__ k,
                       const float* __restrict__ fcos,
                       const float* __restrict__ fsin)
{
    const int QP = SEQ * NH  * (HD / 2);
    const int KP = SEQ * NKV * (HD / 2);
    int idx = blockIdx.x * blockDim.x + threadIdx.x;
    if (idx < QP) {
        int i = idx & 63;
        int h = (idx >> 6) & (NH - 1);
        int s = idx >> 11;
        float c  = fcos[s * 64 + i];
        float sn = fsin[s * 64 + i];
        __half2* p = (__half2*)(q + (size_t)s * DM + h * HD + 2 * i);
        float2 xv = __half22float2(*p);
        *p = __floats2half2_rn(xv.x * c - xv.y * sn, xv.x * sn + xv.y * c);
    } else if (idx < QP + KP) {
        int t = idx - QP;
        int i = t & 63;
        int h = (t >> 6) & (NKV - 1);
        int s = t >> 9;
        float c  = fcos[s * 64 + i];
        float sn = fsin[s * 64 + i];
        __half2* p = (__half2*)(k + (size_t)s * KVD + h * HD + 2 * i);
        float2 xv = __half22float2(*p);
        *p = __floats2half2_rn(xv.x * c - xv.y * sn, xv.x * sn + xv.y * c);
    }
}

// ---------------------------------------------------------------------------
// flash attention v4: BM=128 (8 warps x 16 q rows), BN=64, fp16 mma,
// P-in-registers, cp.async double-buffered K/V. Causal, GQA.
// smem: Q[128][136h] + K[2][64][136h] + V[2][64][136h]
// ---------------------------------------------------------------------------
#define QW  (128*68)               // Q tile words
#define FTW (64*68)                // K/V tile words (4352)
#define FLASH_SMEM ((QW + 4*FTW)*4)   // 104448 B

__global__ __launch_bounds__(256, 1) void flash_h(
    const __half* __restrict__ q, const __half* __restrict__ k,
    const __half* __restrict__ v, __half* __restrict__ outh)
{
    extern __shared__ uint32_t fsm[];
    const uint32_t sb = smem_u32(fsm);

    const int h   = blockIdx.y;
    const int qb  = gridDim.x - 1 - blockIdx.x;   // big tiles first
    const int q0  = qb * 128;
    const int kvh = h >> 2;
    const int tid = threadIdx.x;
    const int warp = tid >> 5;
    const int lane = tid & 31;
    const int l7 = lane & 7, l8 = (lane >> 3) & 1, l16 = lane >> 4;
    const int lg = lane >> 2, lc = lane & 3;

    // loaders: 256 threads, rb = row-within-16, cch = 16B chunk
    const int rb = tid >> 4, cch = tid & 15;

    // stage Q (128 rows) + K/V tile 0
#pragma unroll
    for (int i = 0; i < 8; i++) {
        int r = i * 16 + rb;
        cpa16(sb + (uint32_t)(r * 68 + cch * 4) * 4,
              q + (size_t)(q0 + r) * DM + h * HD + cch * 8);
    }
#pragma unroll
    for (int i = 0; i < 4; i++) {
        int r = i * 16 + rb;
        cpa16(sb + (uint32_t)(QW + r * 68 + cch * 4) * 4,
              k + (size_t)r * KVD + kvh * HD + cch * 8);
        cpa16(sb + (uint32_t)(QW + 2 * FTW + r * 68 + cch * 4) * 4,
              v + (size_t)r * KVD + kvh * HD + cch * 8);
    }
    cp_commit();

    // fragment lane offsets (bytes)
    const uint32_t Qa = (uint32_t)((warp * 16 + l7 + 8 * l8) * 68 + 4 * l16) * 4;
    const uint32_t Kb = (uint32_t)((l7 + 8 * l16) * 68 + 4 * l8) * 4;
    const uint32_t Vb = (uint32_t)((l7 + 8 * l8) * 68 + 4 * l16) * 4;

    float o[16][4];
#pragma unroll
    for (int ni = 0; ni < 16; ni++)
#pragma unroll
        for (int r = 0; r < 4; r++) o[ni][r] = 0.f;
    float m0 = -3.0e38f, m1 = -3.0e38f, l0 = 0.f, l1 = 0.f;

    const float sc = 0.088388347648318447f;   // 1/sqrt(128)
    const int rowl0 = warp * 16 + lg;          // local q row (c0,c1)

    const int kbmax = 2 * qb + 1;
    for (int kb = 0; kb <= kbmax; kb++) {
        const int k0g = kb * 64;
        asm volatile("cp.async.wait_group 0;" ::: "memory");
        __syncthreads();

        if (kb + 1 <= kbmax) {
            const int k0n = (kb + 1) * 64;
            const uint32_t bufn = (uint32_t)((kb + 1) & 1) * FTW;
#pragma unroll
            for (int i = 0; i < 4; i++) {
                int r = i * 16 + rb;
                cpa16(sb + (QW + bufn + (uint32_t)(r * 68 + cch * 4)) * 4,
                      k + (size_t)(k0n + r) * KVD + kvh * HD + cch * 8);
                cpa16(sb + (QW + 2 * FTW + bufn + (uint32_t)(r * 68 + cch * 4)) * 4,
                      v + (size_t)(k0n + r) * KVD + kvh * HD + cch * 8);
            }
            cp_commit();
        }

        const uint32_t bufK = sb + (QW + (uint32_t)(kb & 1) * FTW) * 4;
        const uint32_t bufV = sb + (QW + 2 * FTW + (uint32_t)(kb & 1) * FTW) * 4;

        // S = Q K^T (warp tile 16x64)
        float s[8][4];
#pragma unroll
        for (int ni = 0; ni < 8; ni++)
#pragma unroll
            for (int r = 0; r < 4; r++) s[ni][r] = 0.f;

#pragma unroll
        for (int kd = 0; kd < 8; kd++) {
            uint32_t qa[4];
            ldsm4(qa, sb + Qa + kd * 32);
#pragma unroll
            for (int nj = 0; nj < 4; nj++) {
                uint32_t kb4[4];
                ldsm4(kb4, bufK + Kb + nj * (16 * 68 * 4) + kd * 32);
                mma_f16(s[2 * nj],     qa, kb4);
                mma_f16(s[2 * nj + 1], qa, kb4 + 2);
            }
        }

        // scale + causal mask (only near diagonal for this warp's rows)
        const bool diag = (k0g + 63) > (q0 + warp * 16);
        float mx0 = -3.0e38f, mx1 = -3.0e38f;
#pragma unroll
        for (int ni = 0; ni < 8; ni++) {
            int cl = ni * 8 + 2 * lc;
#pragma unroll
            for (int j = 0; j < 2; j++) {
                float v0 = s[ni][j] * sc;
                float v1 = s[ni][2 + j] * sc;
                if (diag) {
                    if ((k0g + cl + j) > (q0 + rowl0))     v0 += NEG_BIG;
                    if ((k0g + cl + j) > (q0 + rowl0 + 8)) v1 += NEG_BIG;
                }
                s[ni][j] = v0; s[ni][2 + j] = v1;
                mx0 = fmaxf(mx0, v0);
                mx1 = fmaxf(mx1, v1);
            }
        }
        mx0 = fmaxf(mx0, __shfl_xor_sync(0xffffffffu, mx0, 1));
        mx0 = fmaxf(mx0, __shfl_xor_sync(0xffffffffu, mx0, 2));
        mx1 = fmaxf(mx1, __shfl_xor_sync(0xffffffffu, mx1, 1));
        mx1 = fmaxf(mx1, __shfl_xor_sync(0xffffffffu, mx1, 2));

        float mn0 = fmaxf(m0, mx0), mn1 = fmaxf(m1, mx1);
        float a0 = __expf(m0 - mn0), a1 = __expf(m1 - mn1);
        m0 = mn0; m1 = mn1;

        float sum0 = 0.f, sum1 = 0.f;
#pragma unroll
        for (int ni = 0; ni < 8; ni++) {
            float p0 = __expf(s[ni][0] - m0);
            float p1 = __expf(s[ni][1] - m0);
            float p2 = __expf(s[ni][2] - m1);
            float p3 = __expf(s[ni][3] - m1);
            s[ni][0] = p0; s[ni][1] = p1; s[ni][2] = p2; s[ni][3] = p3;
            sum0 += p0 + p1;
            sum1 += p2 + p3;
        }
        sum0 += __shfl_xor_sync(0xffffffffu, sum0, 1);
        sum0 += __shfl_xor_sync(0xffffffffu, sum0, 2);
        sum1 += __shfl_xor_sync(0xffffffffu, sum1, 1);
        sum1 += __shfl_xor_sync(0xffffffffu, sum1, 2);
        l0 = l0 * a0 + sum0;
        l1 = l1 * a1 + sum1;

#pragma unroll
        for (int ni = 0; ni < 16; ni++) {
            o[ni][0] *= a0; o[ni][1] *= a0;
            o[ni][2] *= a1; o[ni][3] *= a1;
        }

        // O += P V
#pragma unroll
        for (int ks = 0; ks < 4; ks++) {
            uint32_t pa[4];
            pa[0] = h2pack(s[2 * ks][0],     s[2 * ks][1]);
            pa[1] = h2pack(s[2 * ks][2],     s[2 * ks][3]);
            pa[2] = h2pack(s[2 * ks + 1][0], s[2 * ks + 1][1]);
            pa[3] = h2pack(s[2 * ks + 1][2], s[2 * ks + 1][3]);
#pragma unroll
            for (int dj = 0; dj < 8; dj++) {
                uint32_t vb4[4];
                ldsm4t(vb4, bufV + Vb + ks * (16 * 68 * 4) + dj * 32);
                mma_f16(o[2 * dj],     pa, vb4);
                mma_f16(o[2 * dj + 1], pa, vb4 + 2);
            }
        }
    }

    const float inv0 = 1.f / l0, inv1 = 1.f / l1;
    __half* ob0 = outh + (size_t)(q0 + rowl0) * DM + h * HD;
    __half* ob1 = ob0 + (size_t)8 * DM;
#pragma unroll
    for (int ni = 0; ni < 16; ni++) {
        int c = ni * 8 + 2 * lc;
        *(uint32_t*)&ob0[c] = h2pack(o[ni][0] * inv0, o[ni][1] * inv0);
        *(uint32_t*)&ob1[c] = h2pack(o[ni][2] * inv1, o[ni][3] * inv1);
    }
}

// ---------------------------------------------------------------------------
extern "C" void kernel_launch(void* const* d_in, const int* in_sizes, int n_in,
                              void* d_out, int out_size)
{
    const float* x    = (const float*)d_in[0];
    const float* wq   = (const float*)d_in[1];
    const float* wk   = (const float*)d_in[2];
    const float* wv   = (const float*)d_in[3];
    const float* wo   = (const float*)d_in[4];
    const float* fcos = (const float*)d_in[7];
    const float* fsin = (const float*)d_in[8];
    float* out = (float*)d_out;

    __half *xh, *wqh, *wkh, *wvh, *woh, *qh, *kh, *vh, *ath;
    cudaGetSymbolAddress((void**)&xh,  g_xh);
    cudaGetSymbolAddress((void**)&wqh, g_wqh);
    cudaGetSymbolAddress((void**)&wkh, g_wkh);
    cudaGetSymbolAddress((void**)&wvh, g_wvh);
    cudaGetSymbolAddress((void**)&woh, g_woh);
    cudaGetSymbolAddress((void**)&qh,  g_qh);
    cudaGetSymbolAddress((void**)&kh,  g_kh);
    cudaGetSymbolAddress((void**)&vh,  g_vh);
    cudaGetSymbolAddress((void**)&ath, g_ath);

    cudaFuncSetAttribute(qkv_gemm,
                         cudaFuncAttributeMaxDynamicSharedMemorySize, GEMM_SMEM);
    cudaFuncSetAttribute(gemm_of,
                         cudaFuncAttributeMaxDynamicSharedMemorySize, GEMM_SMEM);
    cudaFuncSetAttribute(flash_h,
                         cudaFuncAttributeMaxDynamicSharedMemorySize, FLASH_SMEM);

    // fused fp32 -> fp16 conversion (one launch)
    f2h_all<<<(F4_C4 + 255) / 256, 256>>>(x, wq, wk, wv, wo,
                                          xh, wqh, wkh, wvh, woh);

    // fused QKV projection
    qkv_gemm<<<dim3(48, SEQ / 128), 256, GEMM_SMEM>>>(xh, wqh, wkh, wvh,
                                                      qh, kh, vh);

    // RoPE on half q/k
    {
        int total = SEQ * NH * (HD / 2) + SEQ * NKV * (HD / 2);
        rope_h<<<(total + 255) / 256, 256>>>(qh, kh, fcos, fsin);
    }

    // flash attention (fp16 tensor path), BM=128
    flash_h<<<dim3(SEQ / 128, NH), 256, FLASH_SMEM>>>(qh, kh, vh, ath);

    // output projection (half in, float out)
    gemm_of<<<dim3(DM / 128, SEQ / 128), 256, GEMM_SMEM>>>(ath, woh, out,
                                                           SEQ, DM, DM);
}